// round 12
// baseline (speedup 1.0000x reference)
#include <cuda_runtime.h>
#include <cuda_bf16.h>
#include <math.h>
#include <stdint.h>

#define NN 40000
#define NP 40064          // padded rows (313 * 128)
#define NE 640000
#define NG 128
#define NIN 64
#define NH 128
#define NO 256

// ---------------- scratch (device globals; no allocation allowed) ----------------
__device__ __align__(16) __nv_bfloat16 g_xlb[NP * NH];   // xl in bf16 (gathered per edge)
__device__ float g_xr[NP * NH];                          // xr in fp32 (read per node)
__device__ __align__(16) __nv_bfloat16 g_hb[NP * NH];    // agg output (bf16 activations)
__device__ __align__(16) __nv_bfloat16 g_xb[NP * NIN];   // input x in bf16
__device__ __align__(16) __nv_bfloat16 g_bfh[4][256 * 128];  // per-layer effective [N,K] hi
__device__ __align__(16) __nv_bfloat16 g_bfl[4][256 * 128];  // lo
__device__ float g_beff[2][256];                             // folded residual bias terms
__device__ int   g_rowoff[NN + 1];
__device__ int   g_cursor[NN];
__device__ int   g_csrc[NE];
__device__ float g_pool[NG * NH];
__device__ float g_cnt[NG];

__device__ __forceinline__ float lrelu(float v) { return v > 0.f ? v : 0.2f * v; }

__device__ __forceinline__ uint32_t smem_u32(const void* p) {
    uint32_t a;
    asm("{ .reg .u64 t; cvta.to.shared.u64 t, %1; cvt.u32.u64 %0, t; }" : "=r"(a) : "l"(p));
    return a;
}
__device__ __forceinline__ void ldsm4(uint32_t* r, uint32_t addr) {
    asm volatile("ldmatrix.sync.aligned.m8n8.x4.shared.b16 {%0,%1,%2,%3}, [%4];"
                 : "=r"(r[0]), "=r"(r[1]), "=r"(r[2]), "=r"(r[3]) : "r"(addr));
}
__device__ __forceinline__ void mma_bf16(float* d, const uint32_t* a, uint32_t b0, uint32_t b1) {
    asm volatile(
        "mma.sync.aligned.m16n8k16.row.col.f32.bf16.bf16.f32 "
        "{%0,%1,%2,%3}, {%4,%5,%6,%7}, {%8,%9}, {%0,%1,%2,%3};"
        : "+f"(d[0]), "+f"(d[1]), "+f"(d[2]), "+f"(d[3])
        : "r"(a[0]), "r"(a[1]), "r"(a[2]), "r"(a[3]), "r"(b0), "r"(b1));
}
__device__ __forceinline__ void cp16(uint32_t dst, const void* src) {
    asm volatile("cp.async.cg.shared.global [%0], [%1], 16;" :: "r"(dst), "l"(src));
}
#define CP_COMMIT_WAIT() \
    asm volatile("cp.async.commit_group;\ncp.async.wait_group 0;" ::: "memory")

// ---------------- CSR build ----------------
__global__ void hist_kernel(const int* __restrict__ dst, int* __restrict__ cnt) {
    int i = blockIdx.x * blockDim.x + threadIdx.x;
    if (i < NE) atomicAdd(&cnt[dst[i]], 1);
}
__global__ void scan_kernel(const int* __restrict__ cnt, int* __restrict__ rowoff,
                            int* __restrict__ cursor) {
    __shared__ int s_carry;
    __shared__ int warpsums[32];
    int lane = threadIdx.x & 31, wid = threadIdx.x >> 5;
    if (threadIdx.x == 0) s_carry = 0;
    __syncthreads();
    for (int base = 0; base < NN; base += 1024) {
        int i = base + (int)threadIdx.x;
        int v = (i < NN) ? cnt[i] : 0;
        int x = v;
#pragma unroll
        for (int o = 1; o < 32; o <<= 1) {
            int y = __shfl_up_sync(0xFFFFFFFFu, x, o);
            if (lane >= o) x += y;
        }
        if (lane == 31) warpsums[wid] = x;
        __syncthreads();
        if (wid == 0) {
            int w = warpsums[lane];
#pragma unroll
            for (int o = 1; o < 32; o <<= 1) {
                int y = __shfl_up_sync(0xFFFFFFFFu, w, o);
                if (lane >= o) w += y;
            }
            warpsums[lane] = w;
        }
        __syncthreads();
        int incl = x + (wid > 0 ? warpsums[wid - 1] : 0) + s_carry;
        int excl = incl - v;
        if (i < NN) { rowoff[i] = excl; cursor[i] = excl; }
        __syncthreads();
        if (threadIdx.x == 1023) s_carry = incl;
        __syncthreads();
    }
    if (threadIdx.x == 0) rowoff[NN] = NE;
}
__global__ void fill_kernel(const int* __restrict__ src, const int* __restrict__ dst,
                            int* __restrict__ cursor, int* __restrict__ csrc) {
    int i = blockIdx.x * blockDim.x + threadIdx.x;
    if (i >= NE) return;
    int pos = atomicAdd(&cursor[dst[i]], 1);
    csrc[pos] = src[i];
}

// ---------------- weight pack+split (transposed to [N,K]) ----------------
__global__ void pack_fused_kernel(const float* __restrict__ Wl, const float* __restrict__ Wr,
                                  __nv_bfloat16* __restrict__ bh, __nv_bfloat16* __restrict__ bl,
                                  int K) {
    int i = blockIdx.x * blockDim.x + threadIdx.x;
    if (i >= 256 * K) return;
    int n = i / K, k = i % K;
    float v = (n < 128) ? Wl[k * 128 + n] : Wr[k * 128 + (n - 128)];
    __nv_bfloat16 h = __float2bfloat16(v);
    bh[i] = h;
    bl[i] = __float2bfloat16(v - __bfloat162float(h));
}
// Weff = (res_w + I) @ [Wl|Wr], stored [n*128 + k] split hi/lo. grid 128, block 256.
__global__ void weff_kernel(const float* __restrict__ res_w, const float* __restrict__ Wl,
                            const float* __restrict__ Wr, __nv_bfloat16* __restrict__ bh,
                            __nv_bfloat16* __restrict__ bl) {
    __shared__ float a[128];
    int r = blockIdx.x;
    int n = threadIdx.x;
    if (n < 128) {
        float v = res_w[r * 128 + n];
        if (n == r) v += 1.f;
        a[n] = v;
    }
    __syncthreads();
    const float* Wp = (n < 128) ? (Wl + n) : (Wr + (n - 128));
    float s = 0.f;
#pragma unroll 8
    for (int k = 0; k < 128; k++) s += a[k] * Wp[k * 128];
    __nv_bfloat16 h = __float2bfloat16(s);
    bh[n * 128 + r] = h;
    bl[n * 128 + r] = __float2bfloat16(s - __bfloat162float(h));
}
// beff[n] = res_b @ [Wl|Wr] column n. 1 block, 256 threads.
__global__ void beff_kernel(const float* __restrict__ res_b, const float* __restrict__ Wl,
                            const float* __restrict__ Wr, float* __restrict__ beff) {
    __shared__ float b[128];
    int n = threadIdx.x;
    if (n < 128) b[n] = res_b[n];
    __syncthreads();
    const float* Wp = (n < 128) ? (Wl + n) : (Wr + (n - 128));
    float s = 0.f;
#pragma unroll 8
    for (int k = 0; k < 128; k++) s += b[k] * Wp[k * 128];
    beff[n] = s;
}
__global__ void split_x_kernel(const float* __restrict__ x, __nv_bfloat16* __restrict__ hi) {
    int i = blockIdx.x * blockDim.x + threadIdx.x;
    if (i >= NN * NIN) return;
    hi[i] = __float2bfloat16(x[i]);
}

// ---------------- tensor-core GEMM via mma.sync (2-term: Abf16 x (Bhi+Blo)) ----------------
// out cols 0-127 -> bf16 xl (ohi), cols 128-255 -> fp32 xr (outF); optional fp32 bias[256].
template <int K, bool FBIAS>
__global__ void __launch_bounds__(256, 2) mm_gemm(
    const __nv_bfloat16* __restrict__ Ab,
    const __nv_bfloat16* __restrict__ Bh, const __nv_bfloat16* __restrict__ Bl,
    const float* __restrict__ bias, float* __restrict__ outF,
    __nv_bfloat16* __restrict__ ohi) {
    extern __shared__ char smem[];
    constexpr int KC = 64, ST = 72;
    constexpr int TB = 128 * ST;
    __nv_bfloat16* sA = (__nv_bfloat16*)smem;
    __nv_bfloat16* sBh = sA + TB;
    __nv_bfloat16* sBl = sBh + TB;
    int tid = threadIdx.x, lane = tid & 31, wid = tid >> 5;
    int warp_m = wid & 3, warp_n = wid >> 2;
    int bm = blockIdx.x * 128, bn = blockIdx.y * 128;
    const __nv_bfloat16* Bh_blk = Bh + (size_t)bn * K;
    const __nv_bfloat16* Bl_blk = Bl + (size_t)bn * K;

    float acc[2][8][4];
#pragma unroll
    for (int i = 0; i < 2; i++)
#pragma unroll
        for (int j = 0; j < 8; j++)
#pragma unroll
            for (int q = 0; q < 4; q++) acc[i][j][q] = 0.f;

    int g = lane >> 3, lr = lane & 7;
    int frow = lr + ((g & 1) << 3);
    int fcol = (g >> 1) << 3;

    for (int kc = 0; kc < K; kc += KC) {
        if (kc) __syncthreads();
#pragma unroll
        for (int idx = tid; idx < 1024; idx += 256) {
            int r = idx >> 3, c = (idx & 7) * 8;
            cp16(smem_u32(&sA[r * ST + c]), &Ab[(size_t)(bm + r) * K + kc + c]);
            cp16(smem_u32(&sBh[r * ST + c]), &Bh_blk[(size_t)r * K + kc + c]);
            cp16(smem_u32(&sBl[r * ST + c]), &Bl_blk[(size_t)r * K + kc + c]);
        }
        CP_COMMIT_WAIT();
        __syncthreads();
#pragma unroll
        for (int ks = 0; ks < 4; ks++) {
            int kcol = ks * 16 + fcol;
            uint32_t ah0[4], ah1[4];
            ldsm4(ah0, smem_u32(&sA[(warp_m * 32 + frow) * ST + kcol]));
            ldsm4(ah1, smem_u32(&sA[(warp_m * 32 + 16 + frow) * ST + kcol]));
#pragma unroll
            for (int tp = 0; tp < 4; tp++) {
                int brow = warp_n * 64 + tp * 16 + frow;
                uint32_t bh[4], bl[4];
                ldsm4(bh, smem_u32(&sBh[brow * ST + kcol]));
                ldsm4(bl, smem_u32(&sBl[brow * ST + kcol]));
                mma_bf16(acc[0][tp * 2 + 0], ah0, bh[0], bh[2]);
                mma_bf16(acc[0][tp * 2 + 1], ah0, bh[1], bh[3]);
                mma_bf16(acc[1][tp * 2 + 0], ah1, bh[0], bh[2]);
                mma_bf16(acc[1][tp * 2 + 1], ah1, bh[1], bh[3]);
                mma_bf16(acc[0][tp * 2 + 0], ah0, bl[0], bl[2]);
                mma_bf16(acc[0][tp * 2 + 1], ah0, bl[1], bl[3]);
                mma_bf16(acc[1][tp * 2 + 0], ah1, bl[0], bl[2]);
                mma_bf16(acc[1][tp * 2 + 1], ah1, bl[1], bl[3]);
            }
        }
    }

    int lr4 = lane >> 2, lc = (lane & 3) * 2;
#pragma unroll
    for (int tm = 0; tm < 2; tm++) {
#pragma unroll
        for (int half = 0; half < 2; half++) {
            int row = bm + warp_m * 32 + tm * 16 + lr4 + half * 8;
#pragma unroll
            for (int tn = 0; tn < 8; tn++) {
                int gc = bn + warp_n * 64 + tn * 8 + lc;
                float v0 = acc[tm][tn][half * 2 + 0];
                float v1 = acc[tm][tn][half * 2 + 1];
                if (FBIAS) { v0 += bias[gc]; v1 += bias[gc + 1]; }
                if (gc < 128) {  // xl half -> bf16
                    __nv_bfloat162 hv = __floats2bfloat162_rn(v0, v1);
                    *(uint32_t*)&ohi[(size_t)row * NH + gc] = *(uint32_t*)&hv;
                } else {         // xr half -> fp32
                    *(float2*)&outF[(size_t)row * NH + (gc - 128)] = make_float2(v0, v1);
                }
            }
        }
    }
}

// ---------------- fused GAT aggregation: warp per node, plain exp-sum softmax ----------------
// e ~ N(0, ~2): max |e| over 640K edges ~ 15, exp() safely in fp32 range -> no max-shift needed.
__device__ __forceinline__ float4 bf2f4(uint2 u) {
    __nv_bfloat162 p0 = *(__nv_bfloat162*)&u.x;
    __nv_bfloat162 p1 = *(__nv_bfloat162*)&u.y;
    float4 r;
    r.x = __bfloat162float(p0.x);
    r.y = __bfloat162float(p0.y);
    r.z = __bfloat162float(p1.x);
    r.w = __bfloat162float(p1.y);
    return r;
}
__global__ void gat_agg_kernel(const __nv_bfloat16* __restrict__ xlb,
                               const float* __restrict__ xr, const int* __restrict__ rowoff,
                               const int* __restrict__ csrc, const float* __restrict__ att,
                               const float* __restrict__ bias,
                               __nv_bfloat16* __restrict__ ohi,
                               const int* __restrict__ batch, float* __restrict__ pool,
                               float* __restrict__ cnt, float scale) {
    int node = blockIdx.x * 8 + (threadIdx.x >> 5);
    if (node >= NN) return;
    int lane = threadIdx.x & 31;
    const uint2* XB = (const uint2*)xlb;
    float4 xr4 = ((const float4*)xr)[(size_t)node * 32 + lane];
    float4 t = ((const float4*)att)[lane];
    int k = rowoff[node];
    int end = rowoff[node + 1];
    float s0 = 0.f, s1 = 0.f;
    float4 a0 = {0.f, 0.f, 0.f, 0.f}, a1 = {0.f, 0.f, 0.f, 0.f};
    for (; k + 8 <= end; k += 8) {
        float4 xv[8];
        float e[8];
#pragma unroll
        for (int j = 0; j < 8; j++) {
            int sn = csrc[k + j];
            xv[j] = bf2f4(XB[(size_t)sn * 32 + lane]);
        }
#pragma unroll
        for (int j = 0; j < 8; j++) {
            e[j] = lrelu(xv[j].x + xr4.x) * t.x + lrelu(xv[j].y + xr4.y) * t.y +
                   lrelu(xv[j].z + xr4.z) * t.z + lrelu(xv[j].w + xr4.w) * t.w;
        }
#pragma unroll
        for (int o = 16; o; o >>= 1) {
#pragma unroll
            for (int j = 0; j < 8; j++) e[j] += __shfl_xor_sync(0xFFFFFFFFu, e[j], o);
        }
#pragma unroll
        for (int j = 0; j < 8; j += 2) {
            float w0 = __expf(e[j]);
            float w1 = __expf(e[j + 1]);
            s0 += w0;
            s1 += w1;
            a0.x += w0 * xv[j].x;
            a0.y += w0 * xv[j].y;
            a0.z += w0 * xv[j].z;
            a0.w += w0 * xv[j].w;
            a1.x += w1 * xv[j + 1].x;
            a1.y += w1 * xv[j + 1].y;
            a1.z += w1 * xv[j + 1].z;
            a1.w += w1 * xv[j + 1].w;
        }
    }
    for (; k < end; k++) {
        int sn = csrc[k];
        float4 xA = bf2f4(XB[(size_t)sn * 32 + lane]);
        float eA = lrelu(xA.x + xr4.x) * t.x + lrelu(xA.y + xr4.y) * t.y +
                   lrelu(xA.z + xr4.z) * t.z + lrelu(xA.w + xr4.w) * t.w;
#pragma unroll
        for (int o = 16; o; o >>= 1) eA += __shfl_xor_sync(0xFFFFFFFFu, eA, o);
        float w0 = __expf(eA);
        s0 += w0;
        a0.x += w0 * xA.x;
        a0.y += w0 * xA.y;
        a0.z += w0 * xA.z;
        a0.w += w0 * xA.w;
    }
    float s = s0 + s1;
    float inv = 1.f / (s + 1e-16f);
    float4 b4 = ((const float4*)bias)[lane];
    float4 r;
    r.x = fmaxf((a0.x + a1.x) * inv + b4.x, 0.f) * scale;
    r.y = fmaxf((a0.y + a1.y) * inv + b4.y, 0.f) * scale;
    r.z = fmaxf((a0.z + a1.z) * inv + b4.z, 0.f) * scale;
    r.w = fmaxf((a0.w + a1.w) * inv + b4.w, 0.f) * scale;
    if (ohi) {
        __nv_bfloat162 h01 = __floats2bfloat162_rn(r.x, r.y);
        __nv_bfloat162 h23 = __floats2bfloat162_rn(r.z, r.w);
        uint2 uh;
        uh.x = *(uint32_t*)&h01;
        uh.y = *(uint32_t*)&h23;
        ((uint2*)ohi)[(size_t)node * 32 + lane] = uh;
    }
    if (pool) {
        int gidx = batch[node];
        atomicAdd((float4*)(pool + (size_t)gidx * NH + lane * 4), r);
        if (lane == 0) atomicAdd(&cnt[gidx], 1.f);
    }
}

// ---------------- final MLP + layernorm ----------------
__global__ void mlp_kernel(const float* __restrict__ pool, const float* __restrict__ cnt,
                           const float* __restrict__ w1, const float* __restrict__ b1,
                           const float* __restrict__ w2, const float* __restrict__ b2,
                           const float* __restrict__ lng, const float* __restrict__ lnb,
                           float* __restrict__ out) {
    int g = blockIdx.x;
    int t = threadIdx.x;
    __shared__ float p[NH];
    __shared__ float z1[2 * NH];
    __shared__ float rs[8], rq[8];
    float inv = 1.f / fmaxf(cnt[g], 1.f);
    if (t < NH) p[t] = pool[g * NH + t] * inv;
    __syncthreads();
    float a = 0.f;
#pragma unroll 8
    for (int k = 0; k < NH; k++) a += p[k] * w1[k * (2 * NH) + t];
    z1[t] = fmaxf(a + b1[t], 0.f);
    __syncthreads();
    float z = 0.f;
#pragma unroll 8
    for (int k = 0; k < 2 * NH; k++) z += z1[k] * w2[k * NO + t];
    z += b2[t];
    float v = z, v2 = z * z;
#pragma unroll
    for (int o = 16; o; o >>= 1) {
        v += __shfl_xor_sync(0xFFFFFFFFu, v, o);
        v2 += __shfl_xor_sync(0xFFFFFFFFu, v2, o);
    }
    int wid = t >> 5, lane = t & 31;
    if (lane == 0) { rs[wid] = v; rq[wid] = v2; }
    __syncthreads();
    if (wid == 0) {
        float sv = lane < 8 ? rs[lane] : 0.f;
        float sq = lane < 8 ? rq[lane] : 0.f;
#pragma unroll
        for (int o = 4; o; o >>= 1) {
            sv += __shfl_xor_sync(0xFFFFFFFFu, sv, o);
            sq += __shfl_xor_sync(0xFFFFFFFFu, sq, o);
        }
        if (lane == 0) { rs[0] = sv; rq[0] = sq; }
    }
    __syncthreads();
    float mu = rs[0] * (1.f / NO);
    float var = rq[0] * (1.f / NO) - mu * mu;
    out[g * NO + t] = (z - mu) * rsqrtf(var + 1e-5f) * lng[t] + lnb[t];
}

// ---------------- host ----------------
extern "C" void kernel_launch(void* const* d_in, const int* in_sizes, int n_in,
                              void* d_out, int out_size) {
    const float* x = (const float*)d_in[0];
    const int* ei = (const int*)d_in[1];
    const int* src = ei;
    const int* dst = ei + NE;
    const int* batch = (const int*)d_in[2];
    const float* Wl[4] = {(const float*)d_in[3], (const float*)d_in[7],
                          (const float*)d_in[11], (const float*)d_in[15]};
    const float* Wr[4] = {(const float*)d_in[4], (const float*)d_in[8],
                          (const float*)d_in[12], (const float*)d_in[16]};
    const float* att[4] = {(const float*)d_in[5], (const float*)d_in[9],
                           (const float*)d_in[13], (const float*)d_in[17]};
    const float* bb[4] = {(const float*)d_in[6], (const float*)d_in[10],
                          (const float*)d_in[14], (const float*)d_in[18]};
    const float* res_w0 = (const float*)d_in[19];
    const float* res_b0 = (const float*)d_in[20];
    const float* res_w2 = (const float*)d_in[21];
    const float* res_b2 = (const float*)d_in[22];
    const float* mh1_w = (const float*)d_in[23];
    const float* mh1_b = (const float*)d_in[24];
    const float* mh2_w = (const float*)d_in[25];
    const float* mh2_b = (const float*)d_in[26];
    const float* ln_g = (const float*)d_in[27];
    const float* ln_b = (const float*)d_in[28];
    float* out = (float*)d_out;

    float *xr, *pool, *cnt, *beff;
    __nv_bfloat16 *xlb, *hb, *xb, *bfh, *bfl;
    int *rowoff, *cursor, *csrc;
    cudaGetSymbolAddress((void**)&xlb, g_xlb);
    cudaGetSymbolAddress((void**)&xr, g_xr);
    cudaGetSymbolAddress((void**)&hb, g_hb);
    cudaGetSymbolAddress((void**)&xb, g_xb);
    cudaGetSymbolAddress((void**)&bfh, g_bfh);
    cudaGetSymbolAddress((void**)&bfl, g_bfl);
    cudaGetSymbolAddress((void**)&beff, g_beff);
    cudaGetSymbolAddress((void**)&rowoff, g_rowoff);
    cudaGetSymbolAddress((void**)&cursor, g_cursor);
    cudaGetSymbolAddress((void**)&csrc, g_csrc);
    cudaGetSymbolAddress((void**)&pool, g_pool);
    cudaGetSymbolAddress((void**)&cnt, g_cnt);

    // ---- smem attrs (idempotent) ----
    const int SMEM_MM = 3 * 128 * 72 * 2;  // 55296
    cudaFuncSetAttribute(mm_gemm<64, false>, cudaFuncAttributeMaxDynamicSharedMemorySize,
                         SMEM_MM);
    cudaFuncSetAttribute(mm_gemm<128, false>, cudaFuncAttributeMaxDynamicSharedMemorySize,
                         SMEM_MM);
    cudaFuncSetAttribute(mm_gemm<128, true>, cudaFuncAttributeMaxDynamicSharedMemorySize,
                         SMEM_MM);

    const int GT = NP / 128;  // 313
    dim3 gf(GT, 2);
    const int AGG_BLK = (NN + 7) / 8;
    const int SLOT = 256 * 128;

    // ---- single side stream (teardown-safe topology): CSR chain then weight prep ----
    cudaStream_t s2;
    cudaEvent_t evF, evJ2, evJ3;
    cudaStreamCreateWithFlags(&s2, cudaStreamNonBlocking);
    cudaEventCreateWithFlags(&evF, cudaEventDisableTiming);
    cudaEventCreateWithFlags(&evJ2, cudaEventDisableTiming);
    cudaEventCreateWithFlags(&evJ3, cudaEventDisableTiming);
    cudaEventRecord(evF, 0);
    cudaStreamWaitEvent(s2, evF, 0);

    // s2 (phase A): CSR build + pool init -> evJ2
    cudaMemsetAsync(cursor, 0, NN * sizeof(int), s2);
    hist_kernel<<<(NE + 255) / 256, 256, 0, s2>>>(dst, cursor);
    scan_kernel<<<1, 1024, 0, s2>>>(cursor, rowoff, cursor);
    fill_kernel<<<(NE + 255) / 256, 256, 0, s2>>>(src, dst, cursor, csrc);
    cudaMemsetAsync(pool, 0, NG * NH * sizeof(float), s2);
    cudaMemsetAsync(cnt, 0, NG * sizeof(float), s2);
    cudaEventRecord(evJ2, s2);

    // s2 (phase B): effective weights for layers 2..4 -> evJ3
    weff_kernel<<<128, 256, 0, s2>>>(res_w0, Wl[1], Wr[1], bfh + SLOT, bfl + SLOT);
    beff_kernel<<<1, 256, 0, s2>>>(res_b0, Wl[1], Wr[1], beff);
    pack_fused_kernel<<<(256 * NH + 255) / 256, 256, 0, s2>>>(Wl[2], Wr[2], bfh + 2 * SLOT,
                                                              bfl + 2 * SLOT, NH);
    weff_kernel<<<128, 256, 0, s2>>>(res_w2, Wl[3], Wr[3], bfh + 3 * SLOT, bfl + 3 * SLOT);
    beff_kernel<<<1, 256, 0, s2>>>(res_b2, Wl[3], Wr[3], beff + 256);
    cudaEventRecord(evJ3, s2);

    // main stream: layer-1 dependencies + layer-1 GEMM (overlaps with s2)
    pack_fused_kernel<<<(256 * NIN + 255) / 256, 256>>>(Wl[0], Wr[0], bfh, bfl, NIN);
    split_x_kernel<<<(NN * NIN + 255) / 256, 256>>>(x, xb);
    mm_gemm<64, false><<<gf, 256, SMEM_MM>>>(xb, bfh, bfl, nullptr, xr, xlb);

    // join CSR before first agg; join weights before layer-2 GEMM
    cudaStreamWaitEvent(0, evJ2, 0);
    gat_agg_kernel<<<AGG_BLK, 256>>>(xlb, xr, rowoff, csrc, att[0], bb[0], hb, nullptr, nullptr,
                                     nullptr, 1.f);
    cudaStreamWaitEvent(0, evJ3, 0);
    // layer 2 (residual folded into effective weights + beff bias)
    mm_gemm<128, true><<<gf, 256, SMEM_MM>>>(hb, bfh + SLOT, bfl + SLOT, beff, xr, xlb);
    gat_agg_kernel<<<AGG_BLK, 256>>>(xlb, xr, rowoff, csrc, att[1], bb[1], hb, nullptr, nullptr,
                                     nullptr, 2.f);
    // layer 3
    mm_gemm<128, false><<<gf, 256, SMEM_MM>>>(hb, bfh + 2 * SLOT, bfl + 2 * SLOT, nullptr, xr,
                                              xlb);
    gat_agg_kernel<<<AGG_BLK, 256>>>(xlb, xr, rowoff, csrc, att[2], bb[2], hb, nullptr, nullptr,
                                     nullptr, 1.f);
    // layer 4 (residual folded; agg fuses pooling)
    mm_gemm<128, true><<<gf, 256, SMEM_MM>>>(hb, bfh + 3 * SLOT, bfl + 3 * SLOT, beff + 256, xr,
                                             xlb);
    gat_agg_kernel<<<AGG_BLK, 256>>>(xlb, xr, rowoff, csrc, att[3], bb[3], nullptr, batch, pool,
                                     cnt, 2.f);

    // MLP + layernorm
    mlp_kernel<<<NG, 256>>>(pool, cnt, mh1_w, mh1_b, mh2_w, mh2_b, ln_g, ln_b, out);
}

// round 13
// speedup vs baseline: 1.0262x; 1.0262x over previous
#include <cuda_runtime.h>
#include <cuda_bf16.h>
#include <math.h>
#include <stdint.h>

#define NN 40000
#define NP 40064          // padded rows (313 * 128)
#define NE 640000
#define NG 128
#define NIN 64
#define NH 128
#define NO 256

// ---------------- scratch (device globals; no allocation allowed) ----------------
__device__ __align__(16) __nv_bfloat16 g_xlb[NP * NH];   // xl in bf16 (gathered per edge)
__device__ float g_xr[NP * NH];                          // xr in fp32 (read per node)
__device__ __align__(16) __nv_bfloat16 g_hb[NP * NH];    // agg output (bf16 activations)
__device__ __align__(16) __nv_bfloat16 g_xb[NP * NIN];   // input x in bf16
__device__ __align__(16) __nv_bfloat16 g_bfh[4][256 * 128];  // per-layer effective [N,K] hi
__device__ __align__(16) __nv_bfloat16 g_bfl[4][256 * 128];  // lo
__device__ float g_beff[2][256];                             // folded residual bias terms
__device__ int   g_rowoff[NN + 1];
__device__ int   g_cursor[NN];
__device__ int   g_csrc[NE];
__device__ float g_pool[NG * NH];
__device__ float g_cnt[NG];

__device__ __forceinline__ float lrelu(float v) { return v > 0.f ? v : 0.2f * v; }

__device__ __forceinline__ uint32_t smem_u32(const void* p) {
    uint32_t a;
    asm("{ .reg .u64 t; cvta.to.shared.u64 t, %1; cvt.u32.u64 %0, t; }" : "=r"(a) : "l"(p));
    return a;
}
__device__ __forceinline__ void ldsm4(uint32_t* r, uint32_t addr) {
    asm volatile("ldmatrix.sync.aligned.m8n8.x4.shared.b16 {%0,%1,%2,%3}, [%4];"
                 : "=r"(r[0]), "=r"(r[1]), "=r"(r[2]), "=r"(r[3]) : "r"(addr));
}
__device__ __forceinline__ void mma_bf16(float* d, const uint32_t* a, uint32_t b0, uint32_t b1) {
    asm volatile(
        "mma.sync.aligned.m16n8k16.row.col.f32.bf16.bf16.f32 "
        "{%0,%1,%2,%3}, {%4,%5,%6,%7}, {%8,%9}, {%0,%1,%2,%3};"
        : "+f"(d[0]), "+f"(d[1]), "+f"(d[2]), "+f"(d[3])
        : "r"(a[0]), "r"(a[1]), "r"(a[2]), "r"(a[3]), "r"(b0), "r"(b1));
}
__device__ __forceinline__ void cp16(uint32_t dst, const void* src) {
    asm volatile("cp.async.cg.shared.global [%0], [%1], 16;" :: "r"(dst), "l"(src));
}
#define CP_COMMIT_WAIT() \
    asm volatile("cp.async.commit_group;\ncp.async.wait_group 0;" ::: "memory")

// ---------------- CSR build ----------------
__global__ void hist_kernel(const int* __restrict__ dst, int* __restrict__ cnt) {
    int i = blockIdx.x * blockDim.x + threadIdx.x;
    if (i < NE) atomicAdd(&cnt[dst[i]], 1);
}
__global__ void scan_kernel(const int* __restrict__ cnt, int* __restrict__ rowoff,
                            int* __restrict__ cursor) {
    __shared__ int s_carry;
    __shared__ int warpsums[32];
    int lane = threadIdx.x & 31, wid = threadIdx.x >> 5;
    if (threadIdx.x == 0) s_carry = 0;
    __syncthreads();
    for (int base = 0; base < NN; base += 1024) {
        int i = base + (int)threadIdx.x;
        int v = (i < NN) ? cnt[i] : 0;
        int x = v;
#pragma unroll
        for (int o = 1; o < 32; o <<= 1) {
            int y = __shfl_up_sync(0xFFFFFFFFu, x, o);
            if (lane >= o) x += y;
        }
        if (lane == 31) warpsums[wid] = x;
        __syncthreads();
        if (wid == 0) {
            int w = warpsums[lane];
#pragma unroll
            for (int o = 1; o < 32; o <<= 1) {
                int y = __shfl_up_sync(0xFFFFFFFFu, w, o);
                if (lane >= o) w += y;
            }
            warpsums[lane] = w;
        }
        __syncthreads();
        int incl = x + (wid > 0 ? warpsums[wid - 1] : 0) + s_carry;
        int excl = incl - v;
        if (i < NN) { rowoff[i] = excl; cursor[i] = excl; }
        __syncthreads();
        if (threadIdx.x == 1023) s_carry = incl;
        __syncthreads();
    }
    if (threadIdx.x == 0) rowoff[NN] = NE;
}
__global__ void fill_kernel(const int* __restrict__ src, const int* __restrict__ dst,
                            int* __restrict__ cursor, int* __restrict__ csrc) {
    int i = blockIdx.x * blockDim.x + threadIdx.x;
    if (i >= NE) return;
    int pos = atomicAdd(&cursor[dst[i]], 1);
    csrc[pos] = src[i];
}

// ---------------- weight pack+split (transposed to [N,K]) ----------------
__global__ void pack_fused_kernel(const float* __restrict__ Wl, const float* __restrict__ Wr,
                                  __nv_bfloat16* __restrict__ bh, __nv_bfloat16* __restrict__ bl,
                                  int K) {
    int i = blockIdx.x * blockDim.x + threadIdx.x;
    if (i >= 256 * K) return;
    int n = i / K, k = i % K;
    float v = (n < 128) ? Wl[k * 128 + n] : Wr[k * 128 + (n - 128)];
    __nv_bfloat16 h = __float2bfloat16(v);
    bh[i] = h;
    bl[i] = __float2bfloat16(v - __bfloat162float(h));
}
// Weff = (res_w + I) @ [Wl|Wr], stored [n*128 + k] split hi/lo. grid 128, block 256.
__global__ void weff_kernel(const float* __restrict__ res_w, const float* __restrict__ Wl,
                            const float* __restrict__ Wr, __nv_bfloat16* __restrict__ bh,
                            __nv_bfloat16* __restrict__ bl) {
    __shared__ float a[128];
    int r = blockIdx.x;
    int n = threadIdx.x;
    if (n < 128) {
        float v = res_w[r * 128 + n];
        if (n == r) v += 1.f;
        a[n] = v;
    }
    __syncthreads();
    const float* Wp = (n < 128) ? (Wl + n) : (Wr + (n - 128));
    float s = 0.f;
#pragma unroll 8
    for (int k = 0; k < 128; k++) s += a[k] * Wp[k * 128];
    __nv_bfloat16 h = __float2bfloat16(s);
    bh[n * 128 + r] = h;
    bl[n * 128 + r] = __float2bfloat16(s - __bfloat162float(h));
}
// beff[n] = res_b @ [Wl|Wr] column n. 1 block, 256 threads.
__global__ void beff_kernel(const float* __restrict__ res_b, const float* __restrict__ Wl,
                            const float* __restrict__ Wr, float* __restrict__ beff) {
    __shared__ float b[128];
    int n = threadIdx.x;
    if (n < 128) b[n] = res_b[n];
    __syncthreads();
    const float* Wp = (n < 128) ? (Wl + n) : (Wr + (n - 128));
    float s = 0.f;
#pragma unroll 8
    for (int k = 0; k < 128; k++) s += b[k] * Wp[k * 128];
    beff[n] = s;
}
__global__ void split_x_kernel(const float* __restrict__ x, __nv_bfloat16* __restrict__ hi) {
    int i = blockIdx.x * blockDim.x + threadIdx.x;
    if (i >= NN * NIN) return;
    hi[i] = __float2bfloat16(x[i]);
}

// ---------------- tensor-core GEMM via mma.sync (2-term: Abf16 x (Bhi+Blo)) ----------------
// out cols 0-127 -> bf16 xl (ohi), cols 128-255 -> fp32 xr (outF); optional fp32 bias[256].
template <int K, bool FBIAS>
__global__ void __launch_bounds__(256, 2) mm_gemm(
    const __nv_bfloat16* __restrict__ Ab,
    const __nv_bfloat16* __restrict__ Bh, const __nv_bfloat16* __restrict__ Bl,
    const float* __restrict__ bias, float* __restrict__ outF,
    __nv_bfloat16* __restrict__ ohi) {
    extern __shared__ char smem[];
    constexpr int KC = 64, ST = 72;
    constexpr int TB = 128 * ST;
    __nv_bfloat16* sA = (__nv_bfloat16*)smem;
    __nv_bfloat16* sBh = sA + TB;
    __nv_bfloat16* sBl = sBh + TB;
    int tid = threadIdx.x, lane = tid & 31, wid = tid >> 5;
    int warp_m = wid & 3, warp_n = wid >> 2;
    int bm = blockIdx.x * 128, bn = blockIdx.y * 128;
    const __nv_bfloat16* Bh_blk = Bh + (size_t)bn * K;
    const __nv_bfloat16* Bl_blk = Bl + (size_t)bn * K;

    float acc[2][8][4];
#pragma unroll
    for (int i = 0; i < 2; i++)
#pragma unroll
        for (int j = 0; j < 8; j++)
#pragma unroll
            for (int q = 0; q < 4; q++) acc[i][j][q] = 0.f;

    int g = lane >> 3, lr = lane & 7;
    int frow = lr + ((g & 1) << 3);
    int fcol = (g >> 1) << 3;

    for (int kc = 0; kc < K; kc += KC) {
        if (kc) __syncthreads();
#pragma unroll
        for (int idx = tid; idx < 1024; idx += 256) {
            int r = idx >> 3, c = (idx & 7) * 8;
            cp16(smem_u32(&sA[r * ST + c]), &Ab[(size_t)(bm + r) * K + kc + c]);
            cp16(smem_u32(&sBh[r * ST + c]), &Bh_blk[(size_t)r * K + kc + c]);
            cp16(smem_u32(&sBl[r * ST + c]), &Bl_blk[(size_t)r * K + kc + c]);
        }
        CP_COMMIT_WAIT();
        __syncthreads();
#pragma unroll
        for (int ks = 0; ks < 4; ks++) {
            int kcol = ks * 16 + fcol;
            uint32_t ah0[4], ah1[4];
            ldsm4(ah0, smem_u32(&sA[(warp_m * 32 + frow) * ST + kcol]));
            ldsm4(ah1, smem_u32(&sA[(warp_m * 32 + 16 + frow) * ST + kcol]));
#pragma unroll
            for (int tp = 0; tp < 4; tp++) {
                int brow = warp_n * 64 + tp * 16 + frow;
                uint32_t bh[4], bl[4];
                ldsm4(bh, smem_u32(&sBh[brow * ST + kcol]));
                ldsm4(bl, smem_u32(&sBl[brow * ST + kcol]));
                mma_bf16(acc[0][tp * 2 + 0], ah0, bh[0], bh[2]);
                mma_bf16(acc[0][tp * 2 + 1], ah0, bh[1], bh[3]);
                mma_bf16(acc[1][tp * 2 + 0], ah1, bh[0], bh[2]);
                mma_bf16(acc[1][tp * 2 + 1], ah1, bh[1], bh[3]);
                mma_bf16(acc[0][tp * 2 + 0], ah0, bl[0], bl[2]);
                mma_bf16(acc[0][tp * 2 + 1], ah0, bl[1], bl[3]);
                mma_bf16(acc[1][tp * 2 + 0], ah1, bl[0], bl[2]);
                mma_bf16(acc[1][tp * 2 + 1], ah1, bl[1], bl[3]);
            }
        }
    }

    int lr4 = lane >> 2, lc = (lane & 3) * 2;
#pragma unroll
    for (int tm = 0; tm < 2; tm++) {
#pragma unroll
        for (int half = 0; half < 2; half++) {
            int row = bm + warp_m * 32 + tm * 16 + lr4 + half * 8;
#pragma unroll
            for (int tn = 0; tn < 8; tn++) {
                int gc = bn + warp_n * 64 + tn * 8 + lc;
                float v0 = acc[tm][tn][half * 2 + 0];
                float v1 = acc[tm][tn][half * 2 + 1];
                if (FBIAS) { v0 += bias[gc]; v1 += bias[gc + 1]; }
                if (gc < 128) {  // xl half -> bf16
                    __nv_bfloat162 hv = __floats2bfloat162_rn(v0, v1);
                    *(uint32_t*)&ohi[(size_t)row * NH + gc] = *(uint32_t*)&hv;
                } else {         // xr half -> fp32
                    *(float2*)&outF[(size_t)row * NH + (gc - 128)] = make_float2(v0, v1);
                }
            }
        }
    }
}

// ---------------- fused GAT aggregation: warp per node, 4-wide, plain exp-sum ----------------
// e = att . lrelu(.) is a 128-term dot of small weights: |e| stays << 80, so exp() is
// safely in fp32 range without max-shifting (validated: rel_err 6.3e-5 in R12).
__device__ __forceinline__ float4 bf2f4(uint2 u) {
    __nv_bfloat162 p0 = *(__nv_bfloat162*)&u.x;
    __nv_bfloat162 p1 = *(__nv_bfloat162*)&u.y;
    float4 r;
    r.x = __bfloat162float(p0.x);
    r.y = __bfloat162float(p0.y);
    r.z = __bfloat162float(p1.x);
    r.w = __bfloat162float(p1.y);
    return r;
}
__global__ void gat_agg_kernel(const __nv_bfloat16* __restrict__ xlb,
                               const float* __restrict__ xr, const int* __restrict__ rowoff,
                               const int* __restrict__ csrc, const float* __restrict__ att,
                               const float* __restrict__ bias,
                               __nv_bfloat16* __restrict__ ohi,
                               const int* __restrict__ batch, float* __restrict__ pool,
                               float* __restrict__ cnt, float scale) {
    int node = blockIdx.x * 8 + (threadIdx.x >> 5);
    if (node >= NN) return;
    int lane = threadIdx.x & 31;
    const uint2* XB = (const uint2*)xlb;
    float4 xr4 = ((const float4*)xr)[(size_t)node * 32 + lane];
    float4 t = ((const float4*)att)[lane];
    int k = rowoff[node];
    int end = rowoff[node + 1];
    float s0 = 0.f, s1 = 0.f;
    float4 a0 = {0.f, 0.f, 0.f, 0.f}, a1 = {0.f, 0.f, 0.f, 0.f};
    for (; k + 4 <= end; k += 4) {
        int sa = csrc[k], sb = csrc[k + 1], sc = csrc[k + 2], sd = csrc[k + 3];
        float4 xA = bf2f4(XB[(size_t)sa * 32 + lane]);
        float4 xB = bf2f4(XB[(size_t)sb * 32 + lane]);
        float4 xC = bf2f4(XB[(size_t)sc * 32 + lane]);
        float4 xD = bf2f4(XB[(size_t)sd * 32 + lane]);
        float eA = lrelu(xA.x + xr4.x) * t.x + lrelu(xA.y + xr4.y) * t.y +
                   lrelu(xA.z + xr4.z) * t.z + lrelu(xA.w + xr4.w) * t.w;
        float eB = lrelu(xB.x + xr4.x) * t.x + lrelu(xB.y + xr4.y) * t.y +
                   lrelu(xB.z + xr4.z) * t.z + lrelu(xB.w + xr4.w) * t.w;
        float eC = lrelu(xC.x + xr4.x) * t.x + lrelu(xC.y + xr4.y) * t.y +
                   lrelu(xC.z + xr4.z) * t.z + lrelu(xC.w + xr4.w) * t.w;
        float eD = lrelu(xD.x + xr4.x) * t.x + lrelu(xD.y + xr4.y) * t.y +
                   lrelu(xD.z + xr4.z) * t.z + lrelu(xD.w + xr4.w) * t.w;
#pragma unroll
        for (int o = 16; o; o >>= 1) {
            eA += __shfl_xor_sync(0xFFFFFFFFu, eA, o);
            eB += __shfl_xor_sync(0xFFFFFFFFu, eB, o);
            eC += __shfl_xor_sync(0xFFFFFFFFu, eC, o);
            eD += __shfl_xor_sync(0xFFFFFFFFu, eD, o);
        }
        float wA = __expf(eA), wB = __expf(eB), wC = __expf(eC), wD = __expf(eD);
        s0 += wA + wC;
        s1 += wB + wD;
        a0.x += wA * xA.x + wC * xC.x;
        a0.y += wA * xA.y + wC * xC.y;
        a0.z += wA * xA.z + wC * xC.z;
        a0.w += wA * xA.w + wC * xC.w;
        a1.x += wB * xB.x + wD * xD.x;
        a1.y += wB * xB.y + wD * xD.y;
        a1.z += wB * xB.z + wD * xD.z;
        a1.w += wB * xB.w + wD * xD.w;
    }
    for (; k < end; k++) {
        int sn = csrc[k];
        float4 xA = bf2f4(XB[(size_t)sn * 32 + lane]);
        float eA = lrelu(xA.x + xr4.x) * t.x + lrelu(xA.y + xr4.y) * t.y +
                   lrelu(xA.z + xr4.z) * t.z + lrelu(xA.w + xr4.w) * t.w;
#pragma unroll
        for (int o = 16; o; o >>= 1) eA += __shfl_xor_sync(0xFFFFFFFFu, eA, o);
        float wA = __expf(eA);
        s0 += wA;
        a0.x += wA * xA.x;
        a0.y += wA * xA.y;
        a0.z += wA * xA.z;
        a0.w += wA * xA.w;
    }
    float s = s0 + s1;
    float inv = 1.f / (s + 1e-16f);
    float4 b4 = ((const float4*)bias)[lane];
    float4 r;
    r.x = fmaxf((a0.x + a1.x) * inv + b4.x, 0.f) * scale;
    r.y = fmaxf((a0.y + a1.y) * inv + b4.y, 0.f) * scale;
    r.z = fmaxf((a0.z + a1.z) * inv + b4.z, 0.f) * scale;
    r.w = fmaxf((a0.w + a1.w) * inv + b4.w, 0.f) * scale;
    if (ohi) {
        __nv_bfloat162 h01 = __floats2bfloat162_rn(r.x, r.y);
        __nv_bfloat162 h23 = __floats2bfloat162_rn(r.z, r.w);
        uint2 uh;
        uh.x = *(uint32_t*)&h01;
        uh.y = *(uint32_t*)&h23;
        ((uint2*)ohi)[(size_t)node * 32 + lane] = uh;
    }
    if (pool) {
        int gidx = batch[node];
        atomicAdd((float4*)(pool + (size_t)gidx * NH + lane * 4), r);
        if (lane == 0) atomicAdd(&cnt[gidx], 1.f);
    }
}

// ---------------- final MLP + layernorm ----------------
__global__ void mlp_kernel(const float* __restrict__ pool, const float* __restrict__ cnt,
                           const float* __restrict__ w1, const float* __restrict__ b1,
                           const float* __restrict__ w2, const float* __restrict__ b2,
                           const float* __restrict__ lng, const float* __restrict__ lnb,
                           float* __restrict__ out) {
    int g = blockIdx.x;
    int t = threadIdx.x;
    __shared__ float p[NH];
    __shared__ float z1[2 * NH];
    __shared__ float rs[8], rq[8];
    float inv = 1.f / fmaxf(cnt[g], 1.f);
    if (t < NH) p[t] = pool[g * NH + t] * inv;
    __syncthreads();
    float a = 0.f;
#pragma unroll 8
    for (int k = 0; k < NH; k++) a += p[k] * w1[k * (2 * NH) + t];
    z1[t] = fmaxf(a + b1[t], 0.f);
    __syncthreads();
    float z = 0.f;
#pragma unroll 8
    for (int k = 0; k < 2 * NH; k++) z += z1[k] * w2[k * NO + t];
    z += b2[t];
    float v = z, v2 = z * z;
#pragma unroll
    for (int o = 16; o; o >>= 1) {
        v += __shfl_xor_sync(0xFFFFFFFFu, v, o);
        v2 += __shfl_xor_sync(0xFFFFFFFFu, v2, o);
    }
    int wid = t >> 5, lane = t & 31;
    if (lane == 0) { rs[wid] = v; rq[wid] = v2; }
    __syncthreads();
    if (wid == 0) {
        float sv = lane < 8 ? rs[lane] : 0.f;
        float sq = lane < 8 ? rq[lane] : 0.f;
#pragma unroll
        for (int o = 4; o; o >>= 1) {
            sv += __shfl_xor_sync(0xFFFFFFFFu, sv, o);
            sq += __shfl_xor_sync(0xFFFFFFFFu, sq, o);
        }
        if (lane == 0) { rs[0] = sv; rq[0] = sq; }
    }
    __syncthreads();
    float mu = rs[0] * (1.f / NO);
    float var = rq[0] * (1.f / NO) - mu * mu;
    out[g * NO + t] = (z - mu) * rsqrtf(var + 1e-5f) * lng[t] + lnb[t];
}

// ---------------- host ----------------
extern "C" void kernel_launch(void* const* d_in, const int* in_sizes, int n_in,
                              void* d_out, int out_size) {
    const float* x = (const float*)d_in[0];
    const int* ei = (const int*)d_in[1];
    const int* src = ei;
    const int* dst = ei + NE;
    const int* batch = (const int*)d_in[2];
    const float* Wl[4] = {(const float*)d_in[3], (const float*)d_in[7],
                          (const float*)d_in[11], (const float*)d_in[15]};
    const float* Wr[4] = {(const float*)d_in[4], (const float*)d_in[8],
                          (const float*)d_in[12], (const float*)d_in[16]};
    const float* att[4] = {(const float*)d_in[5], (const float*)d_in[9],
                           (const float*)d_in[13], (const float*)d_in[17]};
    const float* bb[4] = {(const float*)d_in[6], (const float*)d_in[10],
                          (const float*)d_in[14], (const float*)d_in[18]};
    const float* res_w0 = (const float*)d_in[19];
    const float* res_b0 = (const float*)d_in[20];
    const float* res_w2 = (const float*)d_in[21];
    const float* res_b2 = (const float*)d_in[22];
    const float* mh1_w = (const float*)d_in[23];
    const float* mh1_b = (const float*)d_in[24];
    const float* mh2_w = (const float*)d_in[25];
    const float* mh2_b = (const float*)d_in[26];
    const float* ln_g = (const float*)d_in[27];
    const float* ln_b = (const float*)d_in[28];
    float* out = (float*)d_out;

    float *xr, *pool, *cnt, *beff;
    __nv_bfloat16 *xlb, *hb, *xb, *bfh, *bfl;
    int *rowoff, *cursor, *csrc;
    cudaGetSymbolAddress((void**)&xlb, g_xlb);
    cudaGetSymbolAddress((void**)&xr, g_xr);
    cudaGetSymbolAddress((void**)&hb, g_hb);
    cudaGetSymbolAddress((void**)&xb, g_xb);
    cudaGetSymbolAddress((void**)&bfh, g_bfh);
    cudaGetSymbolAddress((void**)&bfl, g_bfl);
    cudaGetSymbolAddress((void**)&beff, g_beff);
    cudaGetSymbolAddress((void**)&rowoff, g_rowoff);
    cudaGetSymbolAddress((void**)&cursor, g_cursor);
    cudaGetSymbolAddress((void**)&csrc, g_csrc);
    cudaGetSymbolAddress((void**)&pool, g_pool);
    cudaGetSymbolAddress((void**)&cnt, g_cnt);

    // ---- smem attrs (idempotent) ----
    const int SMEM_MM = 3 * 128 * 72 * 2;  // 55296
    cudaFuncSetAttribute(mm_gemm<64, false>, cudaFuncAttributeMaxDynamicSharedMemorySize,
                         SMEM_MM);
    cudaFuncSetAttribute(mm_gemm<128, false>, cudaFuncAttributeMaxDynamicSharedMemorySize,
                         SMEM_MM);
    cudaFuncSetAttribute(mm_gemm<128, true>, cudaFuncAttributeMaxDynamicSharedMemorySize,
                         SMEM_MM);

    const int GT = NP / 128;  // 313
    dim3 gf(GT, 2);
    const int AGG_BLK = (NN + 7) / 8;
    const int SLOT = 256 * 128;

    // ---- single side stream (teardown-safe topology): CSR chain then weight prep ----
    cudaStream_t s2;
    cudaEvent_t evF, evJ2, evJ3;
    cudaStreamCreateWithFlags(&s2, cudaStreamNonBlocking);
    cudaEventCreateWithFlags(&evF, cudaEventDisableTiming);
    cudaEventCreateWithFlags(&evJ2, cudaEventDisableTiming);
    cudaEventCreateWithFlags(&evJ3, cudaEventDisableTiming);
    cudaEventRecord(evF, 0);
    cudaStreamWaitEvent(s2, evF, 0);

    // s2 (phase A): CSR build + pool init -> evJ2
    cudaMemsetAsync(cursor, 0, NN * sizeof(int), s2);
    hist_kernel<<<(NE + 255) / 256, 256, 0, s2>>>(dst, cursor);
    scan_kernel<<<1, 1024, 0, s2>>>(cursor, rowoff, cursor);
    fill_kernel<<<(NE + 255) / 256, 256, 0, s2>>>(src, dst, cursor, csrc);
    cudaMemsetAsync(pool, 0, NG * NH * sizeof(float), s2);
    cudaMemsetAsync(cnt, 0, NG * sizeof(float), s2);
    cudaEventRecord(evJ2, s2);

    // s2 (phase B): effective weights for layers 2..4 -> evJ3
    weff_kernel<<<128, 256, 0, s2>>>(res_w0, Wl[1], Wr[1], bfh + SLOT, bfl + SLOT);
    beff_kernel<<<1, 256, 0, s2>>>(res_b0, Wl[1], Wr[1], beff);
    pack_fused_kernel<<<(256 * NH + 255) / 256, 256, 0, s2>>>(Wl[2], Wr[2], bfh + 2 * SLOT,
                                                              bfl + 2 * SLOT, NH);
    weff_kernel<<<128, 256, 0, s2>>>(res_w2, Wl[3], Wr[3], bfh + 3 * SLOT, bfl + 3 * SLOT);
    beff_kernel<<<1, 256, 0, s2>>>(res_b2, Wl[3], Wr[3], beff + 256);
    cudaEventRecord(evJ3, s2);

    // main stream: layer-1 dependencies + layer-1 GEMM (overlaps with s2)
    pack_fused_kernel<<<(256 * NIN + 255) / 256, 256>>>(Wl[0], Wr[0], bfh, bfl, NIN);
    split_x_kernel<<<(NN * NIN + 255) / 256, 256>>>(x, xb);
    mm_gemm<64, false><<<gf, 256, SMEM_MM>>>(xb, bfh, bfl, nullptr, xr, xlb);

    // join CSR before first agg; join weights before layer-2 GEMM
    cudaStreamWaitEvent(0, evJ2, 0);
    gat_agg_kernel<<<AGG_BLK, 256>>>(xlb, xr, rowoff, csrc, att[0], bb[0], hb, nullptr, nullptr,
                                     nullptr, 1.f);
    cudaStreamWaitEvent(0, evJ3, 0);
    // layer 2 (residual folded into effective weights + beff bias)
    mm_gemm<128, true><<<gf, 256, SMEM_MM>>>(hb, bfh + SLOT, bfl + SLOT, beff, xr, xlb);
    gat_agg_kernel<<<AGG_BLK, 256>>>(xlb, xr, rowoff, csrc, att[1], bb[1], hb, nullptr, nullptr,
                                     nullptr, 2.f);
    // layer 3
    mm_gemm<128, false><<<gf, 256, SMEM_MM>>>(hb, bfh + 2 * SLOT, bfl + 2 * SLOT, nullptr, xr,
                                              xlb);
    gat_agg_kernel<<<AGG_BLK, 256>>>(xlb, xr, rowoff, csrc, att[2], bb[2], hb, nullptr, nullptr,
                                     nullptr, 1.f);
    // layer 4 (residual folded; agg fuses pooling)
    mm_gemm<128, true><<<gf, 256, SMEM_MM>>>(hb, bfh + 3 * SLOT, bfl + 3 * SLOT, beff + 256, xr,
                                             xlb);
    gat_agg_kernel<<<AGG_BLK, 256>>>(xlb, xr, rowoff, csrc, att[3], bb[3], nullptr, batch, pool,
                                     cnt, 2.f);

    // MLP + layernorm
    mlp_kernel<<<NG, 256>>>(pool, cnt, mh1_w, mh1_b, mh2_w, mh2_b, ln_g, ln_b, out);
}

// round 14
// speedup vs baseline: 1.0404x; 1.0139x over previous
#include <cuda_runtime.h>
#include <cuda_bf16.h>
#include <math.h>
#include <stdint.h>

#define NN 40000
#define NP 40064          // padded rows (313 * 128)
#define NE 640000
#define NG 128
#define NIN 64
#define NH 128
#define NO 256

// ---------------- scratch (device globals; no allocation allowed) ----------------
__device__ __align__(16) __nv_bfloat16 g_xlb[NP * NH];   // xl in bf16 (gathered per edge)
__device__ float g_xr[NP * NH];                          // xr in fp32 (read per node)
__device__ __align__(16) __nv_bfloat16 g_hb[NP * NH];    // agg output (bf16 activations)
__device__ __align__(16) __nv_bfloat16 g_xb[NP * NIN];   // input x in bf16
__device__ __align__(16) __nv_bfloat16 g_bfh[4][256 * 128];  // per-layer effective [N,K] hi
__device__ __align__(16) __nv_bfloat16 g_bfl[4][256 * 128];  // lo
__device__ float g_beff[2][256];                             // folded residual bias terms
__device__ int   g_rowoff[NN + 1];
__device__ int   g_cursor[NN];
__device__ int   g_csrc[NE];
__device__ float g_pool[NG * NH];
__device__ float g_cnt[NG];

__device__ __forceinline__ float lrelu(float v) { return v > 0.f ? v : 0.2f * v; }

__device__ __forceinline__ uint32_t smem_u32(const void* p) {
    uint32_t a;
    asm("{ .reg .u64 t; cvta.to.shared.u64 t, %1; cvt.u32.u64 %0, t; }" : "=r"(a) : "l"(p));
    return a;
}
__device__ __forceinline__ void ldsm4(uint32_t* r, uint32_t addr) {
    asm volatile("ldmatrix.sync.aligned.m8n8.x4.shared.b16 {%0,%1,%2,%3}, [%4];"
                 : "=r"(r[0]), "=r"(r[1]), "=r"(r[2]), "=r"(r[3]) : "r"(addr));
}
__device__ __forceinline__ void mma_bf16(float* d, const uint32_t* a, uint32_t b0, uint32_t b1) {
    asm volatile(
        "mma.sync.aligned.m16n8k16.row.col.f32.bf16.bf16.f32 "
        "{%0,%1,%2,%3}, {%4,%5,%6,%7}, {%8,%9}, {%0,%1,%2,%3};"
        : "+f"(d[0]), "+f"(d[1]), "+f"(d[2]), "+f"(d[3])
        : "r"(a[0]), "r"(a[1]), "r"(a[2]), "r"(a[3]), "r"(b0), "r"(b1));
}
__device__ __forceinline__ void cp16(uint32_t dst, const void* src) {
    asm volatile("cp.async.cg.shared.global [%0], [%1], 16;" :: "r"(dst), "l"(src));
}
#define CP_COMMIT() asm volatile("cp.async.commit_group;" ::: "memory")
#define CP_WAIT(n) asm volatile("cp.async.wait_group %0;" :: "n"(n) : "memory")

// ---------------- CSR build ----------------
__global__ void hist_kernel(const int* __restrict__ dst, int* __restrict__ cnt) {
    int i = blockIdx.x * blockDim.x + threadIdx.x;
    if (i < NE) atomicAdd(&cnt[dst[i]], 1);
}
__global__ void scan_kernel(const int* __restrict__ cnt, int* __restrict__ rowoff,
                            int* __restrict__ cursor) {
    __shared__ int s_carry;
    __shared__ int warpsums[32];
    int lane = threadIdx.x & 31, wid = threadIdx.x >> 5;
    if (threadIdx.x == 0) s_carry = 0;
    __syncthreads();
    for (int base = 0; base < NN; base += 1024) {
        int i = base + (int)threadIdx.x;
        int v = (i < NN) ? cnt[i] : 0;
        int x = v;
#pragma unroll
        for (int o = 1; o < 32; o <<= 1) {
            int y = __shfl_up_sync(0xFFFFFFFFu, x, o);
            if (lane >= o) x += y;
        }
        if (lane == 31) warpsums[wid] = x;
        __syncthreads();
        if (wid == 0) {
            int w = warpsums[lane];
#pragma unroll
            for (int o = 1; o < 32; o <<= 1) {
                int y = __shfl_up_sync(0xFFFFFFFFu, w, o);
                if (lane >= o) w += y;
            }
            warpsums[lane] = w;
        }
        __syncthreads();
        int incl = x + (wid > 0 ? warpsums[wid - 1] : 0) + s_carry;
        int excl = incl - v;
        if (i < NN) { rowoff[i] = excl; cursor[i] = excl; }
        __syncthreads();
        if (threadIdx.x == 1023) s_carry = incl;
        __syncthreads();
    }
    if (threadIdx.x == 0) rowoff[NN] = NE;
}
__global__ void fill_kernel(const int* __restrict__ src, const int* __restrict__ dst,
                            int* __restrict__ cursor, int* __restrict__ csrc) {
    int i = blockIdx.x * blockDim.x + threadIdx.x;
    if (i >= NE) return;
    int pos = atomicAdd(&cursor[dst[i]], 1);
    csrc[pos] = src[i];
}

// ---------------- weight pack+split (transposed to [N,K]) ----------------
__global__ void pack_fused_kernel(const float* __restrict__ Wl, const float* __restrict__ Wr,
                                  __nv_bfloat16* __restrict__ bh, __nv_bfloat16* __restrict__ bl,
                                  int K) {
    int i = blockIdx.x * blockDim.x + threadIdx.x;
    if (i >= 256 * K) return;
    int n = i / K, k = i % K;
    float v = (n < 128) ? Wl[k * 128 + n] : Wr[k * 128 + (n - 128)];
    __nv_bfloat16 h = __float2bfloat16(v);
    bh[i] = h;
    bl[i] = __float2bfloat16(v - __bfloat162float(h));
}
// Weff = (res_w + I) @ [Wl|Wr], stored [n*128 + k] split hi/lo. grid 128, block 256.
__global__ void weff_kernel(const float* __restrict__ res_w, const float* __restrict__ Wl,
                            const float* __restrict__ Wr, __nv_bfloat16* __restrict__ bh,
                            __nv_bfloat16* __restrict__ bl) {
    __shared__ float a[128];
    int r = blockIdx.x;
    int n = threadIdx.x;
    if (n < 128) {
        float v = res_w[r * 128 + n];
        if (n == r) v += 1.f;
        a[n] = v;
    }
    __syncthreads();
    const float* Wp = (n < 128) ? (Wl + n) : (Wr + (n - 128));
    float s = 0.f;
#pragma unroll 8
    for (int k = 0; k < 128; k++) s += a[k] * Wp[k * 128];
    __nv_bfloat16 h = __float2bfloat16(s);
    bh[n * 128 + r] = h;
    bl[n * 128 + r] = __float2bfloat16(s - __bfloat162float(h));
}
// beff[n] = res_b @ [Wl|Wr] column n. 1 block, 256 threads.
__global__ void beff_kernel(const float* __restrict__ res_b, const float* __restrict__ Wl,
                            const float* __restrict__ Wr, float* __restrict__ beff) {
    __shared__ float b[128];
    int n = threadIdx.x;
    if (n < 128) b[n] = res_b[n];
    __syncthreads();
    const float* Wp = (n < 128) ? (Wl + n) : (Wr + (n - 128));
    float s = 0.f;
#pragma unroll 8
    for (int k = 0; k < 128; k++) s += b[k] * Wp[k * 128];
    beff[n] = s;
}
__global__ void split_x_kernel(const float* __restrict__ x, __nv_bfloat16* __restrict__ hi) {
    int i = blockIdx.x * blockDim.x + threadIdx.x;
    if (i >= NN * NIN) return;
    hi[i] = __float2bfloat16(x[i]);
}

// ---------------- tensor-core GEMM via mma.sync (2-term, 2-stage cp.async pipeline) ----------------
// out cols 0-127 -> bf16 xl (ohi), cols 128-255 -> fp32 xr (outF); optional fp32 bias[256].
template <int K, bool FBIAS>
__global__ void __launch_bounds__(256, 2) mm_gemm(
    const __nv_bfloat16* __restrict__ Ab,
    const __nv_bfloat16* __restrict__ Bh, const __nv_bfloat16* __restrict__ Bl,
    const float* __restrict__ bias, float* __restrict__ outF,
    __nv_bfloat16* __restrict__ ohi) {
    extern __shared__ char smem[];
    constexpr int KC = 64, ST = 72;
    constexpr int TB = 128 * ST;      // elems per tile
    constexpr int STAGE = 3 * TB;     // elems per stage (A, Bh, Bl)
    constexpr int NCH = K / KC;       // 1 or 2 chunks
    __nv_bfloat16* sbase = (__nv_bfloat16*)smem;
    int tid = threadIdx.x, lane = tid & 31, wid = tid >> 5;
    int warp_m = wid & 3, warp_n = wid >> 2;
    int bm = blockIdx.x * 128, bn = blockIdx.y * 128;
    const __nv_bfloat16* Bh_blk = Bh + (size_t)bn * K;
    const __nv_bfloat16* Bl_blk = Bl + (size_t)bn * K;

    float acc[2][8][4];
#pragma unroll
    for (int i = 0; i < 2; i++)
#pragma unroll
        for (int j = 0; j < 8; j++)
#pragma unroll
            for (int q = 0; q < 4; q++) acc[i][j][q] = 0.f;

    int g = lane >> 3, lr = lane & 7;
    int frow = lr + ((g & 1) << 3);
    int fcol = (g >> 1) << 3;

    // issue all chunk loads up-front (one commit group per chunk/stage)
#pragma unroll
    for (int c = 0; c < NCH; c++) {
        __nv_bfloat16* sA = sbase + c * STAGE;
        __nv_bfloat16* sBh = sA + TB;
        __nv_bfloat16* sBl = sBh + TB;
        int kc = c * KC;
#pragma unroll
        for (int idx = tid; idx < 1024; idx += 256) {
            int r = idx >> 3, cc = (idx & 7) * 8;
            cp16(smem_u32(&sA[r * ST + cc]), &Ab[(size_t)(bm + r) * K + kc + cc]);
            cp16(smem_u32(&sBh[r * ST + cc]), &Bh_blk[(size_t)r * K + kc + cc]);
            cp16(smem_u32(&sBl[r * ST + cc]), &Bl_blk[(size_t)r * K + kc + cc]);
        }
        CP_COMMIT();
    }

#pragma unroll
    for (int c = 0; c < NCH; c++) {
        if (NCH == 2 && c == 0) CP_WAIT(1);
        else CP_WAIT(0);
        __syncthreads();
        __nv_bfloat16* sA = sbase + c * STAGE;
        __nv_bfloat16* sBh = sA + TB;
        __nv_bfloat16* sBl = sBh + TB;
#pragma unroll
        for (int ks = 0; ks < 4; ks++) {
            int kcol = ks * 16 + fcol;
            uint32_t ah0[4], ah1[4];
            ldsm4(ah0, smem_u32(&sA[(warp_m * 32 + frow) * ST + kcol]));
            ldsm4(ah1, smem_u32(&sA[(warp_m * 32 + 16 + frow) * ST + kcol]));
#pragma unroll
            for (int tp = 0; tp < 4; tp++) {
                int brow = warp_n * 64 + tp * 16 + frow;
                uint32_t bh[4], bl[4];
                ldsm4(bh, smem_u32(&sBh[brow * ST + kcol]));
                ldsm4(bl, smem_u32(&sBl[brow * ST + kcol]));
                mma_bf16(acc[0][tp * 2 + 0], ah0, bh[0], bh[2]);
                mma_bf16(acc[0][tp * 2 + 1], ah0, bh[1], bh[3]);
                mma_bf16(acc[1][tp * 2 + 0], ah1, bh[0], bh[2]);
                mma_bf16(acc[1][tp * 2 + 1], ah1, bh[1], bh[3]);
                mma_bf16(acc[0][tp * 2 + 0], ah0, bl[0], bl[2]);
                mma_bf16(acc[0][tp * 2 + 1], ah0, bl[1], bl[3]);
                mma_bf16(acc[1][tp * 2 + 0], ah1, bl[0], bl[2]);
                mma_bf16(acc[1][tp * 2 + 1], ah1, bl[1], bl[3]);
            }
        }
    }

    int lr4 = lane >> 2, lc = (lane & 3) * 2;
#pragma unroll
    for (int tm = 0; tm < 2; tm++) {
#pragma unroll
        for (int half = 0; half < 2; half++) {
            int row = bm + warp_m * 32 + tm * 16 + lr4 + half * 8;
#pragma unroll
            for (int tn = 0; tn < 8; tn++) {
                int gc = bn + warp_n * 64 + tn * 8 + lc;
                float v0 = acc[tm][tn][half * 2 + 0];
                float v1 = acc[tm][tn][half * 2 + 1];
                if (FBIAS) { v0 += bias[gc]; v1 += bias[gc + 1]; }
                if (gc < 128) {  // xl half -> bf16
                    __nv_bfloat162 hv = __floats2bfloat162_rn(v0, v1);
                    *(uint32_t*)&ohi[(size_t)row * NH + gc] = *(uint32_t*)&hv;
                } else {         // xr half -> fp32
                    *(float2*)&outF[(size_t)row * NH + (gc - 128)] = make_float2(v0, v1);
                }
            }
        }
    }
}

// ---------------- fused GAT aggregation: warp per node, 4-wide, plain exp-sum ----------------
// e = att . lrelu(.) is a 128-term dot of small weights: |e| stays << 80, so exp() is
// safely in fp32 range without max-shifting (validated: rel_err 6.3e-5).
__device__ __forceinline__ float4 bf2f4(uint2 u) {
    __nv_bfloat162 p0 = *(__nv_bfloat162*)&u.x;
    __nv_bfloat162 p1 = *(__nv_bfloat162*)&u.y;
    float4 r;
    r.x = __bfloat162float(p0.x);
    r.y = __bfloat162float(p0.y);
    r.z = __bfloat162float(p1.x);
    r.w = __bfloat162float(p1.y);
    return r;
}
__global__ void gat_agg_kernel(const __nv_bfloat16* __restrict__ xlb,
                               const float* __restrict__ xr, const int* __restrict__ rowoff,
                               const int* __restrict__ csrc, const float* __restrict__ att,
                               const float* __restrict__ bias,
                               __nv_bfloat16* __restrict__ ohi,
                               const int* __restrict__ batch, float* __restrict__ pool,
                               float* __restrict__ cnt, float scale) {
    int node = blockIdx.x * 8 + (threadIdx.x >> 5);
    if (node >= NN) return;
    int lane = threadIdx.x & 31;
    const uint2* XB = (const uint2*)xlb;
    float4 xr4 = ((const float4*)xr)[(size_t)node * 32 + lane];
    float4 t = ((const float4*)att)[lane];
    int k = rowoff[node];
    int end = rowoff[node + 1];
    float s0 = 0.f, s1 = 0.f;
    float4 a0 = {0.f, 0.f, 0.f, 0.f}, a1 = {0.f, 0.f, 0.f, 0.f};
    for (; k + 4 <= end; k += 4) {
        int sa = csrc[k], sb = csrc[k + 1], sc = csrc[k + 2], sd = csrc[k + 3];
        float4 xA = bf2f4(XB[(size_t)sa * 32 + lane]);
        float4 xB = bf2f4(XB[(size_t)sb * 32 + lane]);
        float4 xC = bf2f4(XB[(size_t)sc * 32 + lane]);
        float4 xD = bf2f4(XB[(size_t)sd * 32 + lane]);
        float eA = lrelu(xA.x + xr4.x) * t.x + lrelu(xA.y + xr4.y) * t.y +
                   lrelu(xA.z + xr4.z) * t.z + lrelu(xA.w + xr4.w) * t.w;
        float eB = lrelu(xB.x + xr4.x) * t.x + lrelu(xB.y + xr4.y) * t.y +
                   lrelu(xB.z + xr4.z) * t.z + lrelu(xB.w + xr4.w) * t.w;
        float eC = lrelu(xC.x + xr4.x) * t.x + lrelu(xC.y + xr4.y) * t.y +
                   lrelu(xC.z + xr4.z) * t.z + lrelu(xC.w + xr4.w) * t.w;
        float eD = lrelu(xD.x + xr4.x) * t.x + lrelu(xD.y + xr4.y) * t.y +
                   lrelu(xD.z + xr4.z) * t.z + lrelu(xD.w + xr4.w) * t.w;
#pragma unroll
        for (int o = 16; o; o >>= 1) {
            eA += __shfl_xor_sync(0xFFFFFFFFu, eA, o);
            eB += __shfl_xor_sync(0xFFFFFFFFu, eB, o);
            eC += __shfl_xor_sync(0xFFFFFFFFu, eC, o);
            eD += __shfl_xor_sync(0xFFFFFFFFu, eD, o);
        }
        float wA = __expf(eA), wB = __expf(eB), wC = __expf(eC), wD = __expf(eD);
        s0 += wA + wC;
        s1 += wB + wD;
        a0.x += wA * xA.x + wC * xC.x;
        a0.y += wA * xA.y + wC * xC.y;
        a0.z += wA * xA.z + wC * xC.z;
        a0.w += wA * xA.w + wC * xC.w;
        a1.x += wB * xB.x + wD * xD.x;
        a1.y += wB * xB.y + wD * xD.y;
        a1.z += wB * xB.z + wD * xD.z;
        a1.w += wB * xB.w + wD * xD.w;
    }
    for (; k < end; k++) {
        int sn = csrc[k];
        float4 xA = bf2f4(XB[(size_t)sn * 32 + lane]);
        float eA = lrelu(xA.x + xr4.x) * t.x + lrelu(xA.y + xr4.y) * t.y +
                   lrelu(xA.z + xr4.z) * t.z + lrelu(xA.w + xr4.w) * t.w;
#pragma unroll
        for (int o = 16; o; o >>= 1) eA += __shfl_xor_sync(0xFFFFFFFFu, eA, o);
        float wA = __expf(eA);
        s0 += wA;
        a0.x += wA * xA.x;
        a0.y += wA * xA.y;
        a0.z += wA * xA.z;
        a0.w += wA * xA.w;
    }
    float s = s0 + s1;
    float inv = 1.f / (s + 1e-16f);
    float4 b4 = ((const float4*)bias)[lane];
    float4 r;
    r.x = fmaxf((a0.x + a1.x) * inv + b4.x, 0.f) * scale;
    r.y = fmaxf((a0.y + a1.y) * inv + b4.y, 0.f) * scale;
    r.z = fmaxf((a0.z + a1.z) * inv + b4.z, 0.f) * scale;
    r.w = fmaxf((a0.w + a1.w) * inv + b4.w, 0.f) * scale;
    if (ohi) {
        __nv_bfloat162 h01 = __floats2bfloat162_rn(r.x, r.y);
        __nv_bfloat162 h23 = __floats2bfloat162_rn(r.z, r.w);
        uint2 uh;
        uh.x = *(uint32_t*)&h01;
        uh.y = *(uint32_t*)&h23;
        ((uint2*)ohi)[(size_t)node * 32 + lane] = uh;
    }
    if (pool) {
        int gidx = batch[node];
        atomicAdd((float4*)(pool + (size_t)gidx * NH + lane * 4), r);
        if (lane == 0) atomicAdd(&cnt[gidx], 1.f);
    }
}

// ---------------- final MLP + layernorm ----------------
__global__ void mlp_kernel(const float* __restrict__ pool, const float* __restrict__ cnt,
                           const float* __restrict__ w1, const float* __restrict__ b1,
                           const float* __restrict__ w2, const float* __restrict__ b2,
                           const float* __restrict__ lng, const float* __restrict__ lnb,
                           float* __restrict__ out) {
    int g = blockIdx.x;
    int t = threadIdx.x;
    __shared__ float p[NH];
    __shared__ float z1[2 * NH];
    __shared__ float rs[8], rq[8];
    float inv = 1.f / fmaxf(cnt[g], 1.f);
    if (t < NH) p[t] = pool[g * NH + t] * inv;
    __syncthreads();
    float a = 0.f;
#pragma unroll 8
    for (int k = 0; k < NH; k++) a += p[k] * w1[k * (2 * NH) + t];
    z1[t] = fmaxf(a + b1[t], 0.f);
    __syncthreads();
    float z = 0.f;
#pragma unroll 8
    for (int k = 0; k < 2 * NH; k++) z += z1[k] * w2[k * NO + t];
    z += b2[t];
    float v = z, v2 = z * z;
#pragma unroll
    for (int o = 16; o; o >>= 1) {
        v += __shfl_xor_sync(0xFFFFFFFFu, v, o);
        v2 += __shfl_xor_sync(0xFFFFFFFFu, v2, o);
    }
    int wid = t >> 5, lane = t & 31;
    if (lane == 0) { rs[wid] = v; rq[wid] = v2; }
    __syncthreads();
    if (wid == 0) {
        float sv = lane < 8 ? rs[lane] : 0.f;
        float sq = lane < 8 ? rq[lane] : 0.f;
#pragma unroll
        for (int o = 4; o; o >>= 1) {
            sv += __shfl_xor_sync(0xFFFFFFFFu, sv, o);
            sq += __shfl_xor_sync(0xFFFFFFFFu, sq, o);
        }
        if (lane == 0) { rs[0] = sv; rq[0] = sq; }
    }
    __syncthreads();
    float mu = rs[0] * (1.f / NO);
    float var = rq[0] * (1.f / NO) - mu * mu;
    out[g * NO + t] = (z - mu) * rsqrtf(var + 1e-5f) * lng[t] + lnb[t];
}

// ---------------- host ----------------
extern "C" void kernel_launch(void* const* d_in, const int* in_sizes, int n_in,
                              void* d_out, int out_size) {
    const float* x = (const float*)d_in[0];
    const int* ei = (const int*)d_in[1];
    const int* src = ei;
    const int* dst = ei + NE;
    const int* batch = (const int*)d_in[2];
    const float* Wl[4] = {(const float*)d_in[3], (const float*)d_in[7],
                          (const float*)d_in[11], (const float*)d_in[15]};
    const float* Wr[4] = {(const float*)d_in[4], (const float*)d_in[8],
                          (const float*)d_in[12], (const float*)d_in[16]};
    const float* att[4] = {(const float*)d_in[5], (const float*)d_in[9],
                           (const float*)d_in[13], (const float*)d_in[17]};
    const float* bb[4] = {(const float*)d_in[6], (const float*)d_in[10],
                          (const float*)d_in[14], (const float*)d_in[18]};
    const float* res_w0 = (const float*)d_in[19];
    const float* res_b0 = (const float*)d_in[20];
    const float* res_w2 = (const float*)d_in[21];
    const float* res_b2 = (const float*)d_in[22];
    const float* mh1_w = (const float*)d_in[23];
    const float* mh1_b = (const float*)d_in[24];
    const float* mh2_w = (const float*)d_in[25];
    const float* mh2_b = (const float*)d_in[26];
    const float* ln_g = (const float*)d_in[27];
    const float* ln_b = (const float*)d_in[28];
    float* out = (float*)d_out;

    float *xr, *pool, *cnt, *beff;
    __nv_bfloat16 *xlb, *hb, *xb, *bfh, *bfl;
    int *rowoff, *cursor, *csrc;
    cudaGetSymbolAddress((void**)&xlb, g_xlb);
    cudaGetSymbolAddress((void**)&xr, g_xr);
    cudaGetSymbolAddress((void**)&hb, g_hb);
    cudaGetSymbolAddress((void**)&xb, g_xb);
    cudaGetSymbolAddress((void**)&bfh, g_bfh);
    cudaGetSymbolAddress((void**)&bfl, g_bfl);
    cudaGetSymbolAddress((void**)&beff, g_beff);
    cudaGetSymbolAddress((void**)&rowoff, g_rowoff);
    cudaGetSymbolAddress((void**)&cursor, g_cursor);
    cudaGetSymbolAddress((void**)&csrc, g_csrc);
    cudaGetSymbolAddress((void**)&pool, g_pool);
    cudaGetSymbolAddress((void**)&cnt, g_cnt);

    // ---- smem attrs (idempotent): 2 stages x 3 tiles x 18432 B ----
    const int SMEM_MM = 2 * 3 * 128 * 72 * 2;  // 110592
    cudaFuncSetAttribute(mm_gemm<64, false>, cudaFuncAttributeMaxDynamicSharedMemorySize,
                         SMEM_MM);
    cudaFuncSetAttribute(mm_gemm<128, false>, cudaFuncAttributeMaxDynamicSharedMemorySize,
                         SMEM_MM);
    cudaFuncSetAttribute(mm_gemm<128, true>, cudaFuncAttributeMaxDynamicSharedMemorySize,
                         SMEM_MM);

    const int GT = NP / 128;  // 313
    dim3 gf(GT, 2);
    const int AGG_BLK = (NN + 7) / 8;
    const int SLOT = 256 * 128;

    // ---- single side stream (teardown-safe topology): CSR chain then weight prep ----
    cudaStream_t s2;
    cudaEvent_t evF, evJ2, evJ3;
    cudaStreamCreateWithFlags(&s2, cudaStreamNonBlocking);
    cudaEventCreateWithFlags(&evF, cudaEventDisableTiming);
    cudaEventCreateWithFlags(&evJ2, cudaEventDisableTiming);
    cudaEventCreateWithFlags(&evJ3, cudaEventDisableTiming);
    cudaEventRecord(evF, 0);
    cudaStreamWaitEvent(s2, evF, 0);

    // s2 (phase A): CSR build -> evJ2 (pool init deferred to phase B; only agg-4 needs it)
    cudaMemsetAsync(cursor, 0, NN * sizeof(int), s2);
    hist_kernel<<<(NE + 255) / 256, 256, 0, s2>>>(dst, cursor);
    scan_kernel<<<1, 1024, 0, s2>>>(cursor, rowoff, cursor);
    fill_kernel<<<(NE + 255) / 256, 256, 0, s2>>>(src, dst, cursor, csrc);
    cudaEventRecord(evJ2, s2);

    // s2 (phase B): pool init + effective weights for layers 2..4 -> evJ3
    cudaMemsetAsync(pool, 0, NG * NH * sizeof(float), s2);
    cudaMemsetAsync(cnt, 0, NG * sizeof(float), s2);
    weff_kernel<<<128, 256, 0, s2>>>(res_w0, Wl[1], Wr[1], bfh + SLOT, bfl + SLOT);
    beff_kernel<<<1, 256, 0, s2>>>(res_b0, Wl[1], Wr[1], beff);
    pack_fused_kernel<<<(256 * NH + 255) / 256, 256, 0, s2>>>(Wl[2], Wr[2], bfh + 2 * SLOT,
                                                              bfl + 2 * SLOT, NH);
    weff_kernel<<<128, 256, 0, s2>>>(res_w2, Wl[3], Wr[3], bfh + 3 * SLOT, bfl + 3 * SLOT);
    beff_kernel<<<1, 256, 0, s2>>>(res_b2, Wl[3], Wr[3], beff + 256);
    cudaEventRecord(evJ3, s2);

    // main stream: layer-1 dependencies + layer-1 GEMM (overlaps with s2)
    pack_fused_kernel<<<(256 * NIN + 255) / 256, 256>>>(Wl[0], Wr[0], bfh, bfl, NIN);
    split_x_kernel<<<(NN * NIN + 255) / 256, 256>>>(x, xb);
    mm_gemm<64, false><<<gf, 256, SMEM_MM>>>(xb, bfh, bfl, nullptr, xr, xlb);

    // join CSR before first agg; join weights before layer-2 GEMM
    cudaStreamWaitEvent(0, evJ2, 0);
    gat_agg_kernel<<<AGG_BLK, 256>>>(xlb, xr, rowoff, csrc, att[0], bb[0], hb, nullptr, nullptr,
                                     nullptr, 1.f);
    cudaStreamWaitEvent(0, evJ3, 0);
    // layer 2 (residual folded into effective weights + beff bias)
    mm_gemm<128, true><<<gf, 256, SMEM_MM>>>(hb, bfh + SLOT, bfl + SLOT, beff, xr, xlb);
    gat_agg_kernel<<<AGG_BLK, 256>>>(xlb, xr, rowoff, csrc, att[1], bb[1], hb, nullptr, nullptr,
                                     nullptr, 2.f);
    // layer 3
    mm_gemm<128, false><<<gf, 256, SMEM_MM>>>(hb, bfh + 2 * SLOT, bfl + 2 * SLOT, nullptr, xr,
                                              xlb);
    gat_agg_kernel<<<AGG_BLK, 256>>>(xlb, xr, rowoff, csrc, att[2], bb[2], hb, nullptr, nullptr,
                                     nullptr, 1.f);
    // layer 4 (residual folded; agg fuses pooling)
    mm_gemm<128, true><<<gf, 256, SMEM_MM>>>(hb, bfh + 3 * SLOT, bfl + 3 * SLOT, beff + 256, xr,
                                             xlb);
    gat_agg_kernel<<<AGG_BLK, 256>>>(xlb, xr, rowoff, csrc, att[3], bb[3], nullptr, batch, pool,
                                     cnt, 2.f);

    // MLP + layernorm
    mlp_kernel<<<NG, 256>>>(pool, cnt, mh1_w, mh1_b, mh2_w, mh2_b, ln_g, ln_b, out);
}

// round 15
// speedup vs baseline: 1.0504x; 1.0095x over previous
#include <cuda_runtime.h>
#include <cuda_bf16.h>
#include <math.h>
#include <stdint.h>

#define NN 40000
#define NP 40064          // padded rows (313 * 128)
#define NE 640000
#define NG 128
#define NIN 64
#define NH 128
#define NO 256

// ---------------- scratch (device globals; no allocation allowed) ----------------
__device__ __align__(16) __nv_bfloat16 g_xlb[NP * NH];   // xl in bf16 (gathered per edge)
__device__ float g_xr[NP * NH];                          // xr in fp32 (read per node)
__device__ __align__(16) __nv_bfloat16 g_hb[NP * NH];    // agg output (bf16 activations)
__device__ __align__(16) __nv_bfloat16 g_xb[NP * NIN];   // input x in bf16
__device__ __align__(16) __nv_bfloat16 g_bfh[4][256 * 128];  // per-layer effective [N,K] hi
__device__ __align__(16) __nv_bfloat16 g_bfl[4][256 * 128];  // lo
__device__ float g_beff[2][256];                             // folded residual bias terms
__device__ int   g_rowoff[NN + 1];
__device__ int   g_cursor[NN];
__device__ int   g_csrc[NE];
__device__ float g_pool[NG * NH];
__device__ float g_cnt[NG];

__device__ __forceinline__ float lrelu(float v) { return v > 0.f ? v : 0.2f * v; }

__device__ __forceinline__ uint32_t smem_u32(const void* p) {
    uint32_t a;
    asm("{ .reg .u64 t; cvta.to.shared.u64 t, %1; cvt.u32.u64 %0, t; }" : "=r"(a) : "l"(p));
    return a;
}
__device__ __forceinline__ void ldsm4(uint32_t* r, uint32_t addr) {
    asm volatile("ldmatrix.sync.aligned.m8n8.x4.shared.b16 {%0,%1,%2,%3}, [%4];"
                 : "=r"(r[0]), "=r"(r[1]), "=r"(r[2]), "=r"(r[3]) : "r"(addr));
}
__device__ __forceinline__ void mma_bf16(float* d, const uint32_t* a, uint32_t b0, uint32_t b1) {
    asm volatile(
        "mma.sync.aligned.m16n8k16.row.col.f32.bf16.bf16.f32 "
        "{%0,%1,%2,%3}, {%4,%5,%6,%7}, {%8,%9}, {%0,%1,%2,%3};"
        : "+f"(d[0]), "+f"(d[1]), "+f"(d[2]), "+f"(d[3])
        : "r"(a[0]), "r"(a[1]), "r"(a[2]), "r"(a[3]), "r"(b0), "r"(b1));
}
__device__ __forceinline__ void cp16(uint32_t dst, const void* src) {
    asm volatile("cp.async.cg.shared.global [%0], [%1], 16;" :: "r"(dst), "l"(src));
}
#define CP_COMMIT() asm volatile("cp.async.commit_group;" ::: "memory")
#define CP_WAIT(n) asm volatile("cp.async.wait_group %0;" :: "n"(n) : "memory")

// ---------------- CSR build ----------------
__global__ void hist_kernel(const int* __restrict__ dst, int* __restrict__ cnt) {
    int i = blockIdx.x * blockDim.x + threadIdx.x;
    if (i < NE) atomicAdd(&cnt[dst[i]], 1);
}
__global__ void scan_kernel(const int* __restrict__ cnt, int* __restrict__ rowoff,
                            int* __restrict__ cursor) {
    __shared__ int s_carry;
    __shared__ int warpsums[32];
    int lane = threadIdx.x & 31, wid = threadIdx.x >> 5;
    if (threadIdx.x == 0) s_carry = 0;
    __syncthreads();
    for (int base = 0; base < NN; base += 1024) {
        int i = base + (int)threadIdx.x;
        int v = (i < NN) ? cnt[i] : 0;
        int x = v;
#pragma unroll
        for (int o = 1; o < 32; o <<= 1) {
            int y = __shfl_up_sync(0xFFFFFFFFu, x, o);
            if (lane >= o) x += y;
        }
        if (lane == 31) warpsums[wid] = x;
        __syncthreads();
        if (wid == 0) {
            int w = warpsums[lane];
#pragma unroll
            for (int o = 1; o < 32; o <<= 1) {
                int y = __shfl_up_sync(0xFFFFFFFFu, w, o);
                if (lane >= o) w += y;
            }
            warpsums[lane] = w;
        }
        __syncthreads();
        int incl = x + (wid > 0 ? warpsums[wid - 1] : 0) + s_carry;
        int excl = incl - v;
        if (i < NN) { rowoff[i] = excl; cursor[i] = excl; }
        __syncthreads();
        if (threadIdx.x == 1023) s_carry = incl;
        __syncthreads();
    }
    if (threadIdx.x == 0) rowoff[NN] = NE;
}
__global__ void fill_kernel(const int* __restrict__ src, const int* __restrict__ dst,
                            int* __restrict__ cursor, int* __restrict__ csrc) {
    int i = blockIdx.x * blockDim.x + threadIdx.x;
    if (i >= NE) return;
    int pos = atomicAdd(&cursor[dst[i]], 1);
    csrc[pos] = src[i];
}

// ---------------- weight pack+split (transposed to [N,K]) ----------------
__global__ void pack_fused_kernel(const float* __restrict__ Wl, const float* __restrict__ Wr,
                                  __nv_bfloat16* __restrict__ bh, __nv_bfloat16* __restrict__ bl,
                                  int K) {
    int i = blockIdx.x * blockDim.x + threadIdx.x;
    if (i >= 256 * K) return;
    int n = i / K, k = i % K;
    float v = (n < 128) ? Wl[k * 128 + n] : Wr[k * 128 + (n - 128)];
    __nv_bfloat16 h = __float2bfloat16(v);
    bh[i] = h;
    bl[i] = __float2bfloat16(v - __bfloat162float(h));
}
// Weff = (res_w + I) @ [Wl|Wr], stored [n*128 + k] split hi/lo. grid 128, block 256.
__global__ void weff_kernel(const float* __restrict__ res_w, const float* __restrict__ Wl,
                            const float* __restrict__ Wr, __nv_bfloat16* __restrict__ bh,
                            __nv_bfloat16* __restrict__ bl) {
    __shared__ float a[128];
    int r = blockIdx.x;
    int n = threadIdx.x;
    if (n < 128) {
        float v = res_w[r * 128 + n];
        if (n == r) v += 1.f;
        a[n] = v;
    }
    __syncthreads();
    const float* Wp = (n < 128) ? (Wl + n) : (Wr + (n - 128));
    float s = 0.f;
#pragma unroll 8
    for (int k = 0; k < 128; k++) s += a[k] * Wp[k * 128];
    __nv_bfloat16 h = __float2bfloat16(s);
    bh[n * 128 + r] = h;
    bl[n * 128 + r] = __float2bfloat16(s - __bfloat162float(h));
}
// beff[n] = res_b @ [Wl|Wr] column n. 1 block, 256 threads.
__global__ void beff_kernel(const float* __restrict__ res_b, const float* __restrict__ Wl,
                            const float* __restrict__ Wr, float* __restrict__ beff) {
    __shared__ float b[128];
    int n = threadIdx.x;
    if (n < 128) b[n] = res_b[n];
    __syncthreads();
    const float* Wp = (n < 128) ? (Wl + n) : (Wr + (n - 128));
    float s = 0.f;
#pragma unroll 8
    for (int k = 0; k < 128; k++) s += b[k] * Wp[k * 128];
    beff[n] = s;
}
__global__ void split_x_kernel(const float* __restrict__ x, __nv_bfloat16* __restrict__ hi) {
    int i = blockIdx.x * blockDim.x + threadIdx.x;
    if (i >= NN * NIN) return;
    hi[i] = __float2bfloat16(x[i]);
}

// ---------------- tensor-core GEMM via mma.sync (2-term, 2-stage cp.async pipeline) ----------------
// out cols 0-127 -> bf16 xl (ohi), cols 128-255 -> fp32 xr (outF); optional fp32 bias[256].
template <int K, bool FBIAS>
__global__ void __launch_bounds__(256, 2) mm_gemm(
    const __nv_bfloat16* __restrict__ Ab,
    const __nv_bfloat16* __restrict__ Bh, const __nv_bfloat16* __restrict__ Bl,
    const float* __restrict__ bias, float* __restrict__ outF,
    __nv_bfloat16* __restrict__ ohi) {
    extern __shared__ char smem[];
    constexpr int KC = 64, ST = 72;
    constexpr int TB = 128 * ST;      // elems per tile
    constexpr int STAGE = 3 * TB;     // elems per stage (A, Bh, Bl)
    constexpr int NCH = K / KC;       // 1 or 2 chunks
    __nv_bfloat16* sbase = (__nv_bfloat16*)smem;
    int tid = threadIdx.x, lane = tid & 31, wid = tid >> 5;
    int warp_m = wid & 3, warp_n = wid >> 2;
    int bm = blockIdx.x * 128, bn = blockIdx.y * 128;
    const __nv_bfloat16* Bh_blk = Bh + (size_t)bn * K;
    const __nv_bfloat16* Bl_blk = Bl + (size_t)bn * K;

    float acc[2][8][4];
#pragma unroll
    for (int i = 0; i < 2; i++)
#pragma unroll
        for (int j = 0; j < 8; j++)
#pragma unroll
            for (int q = 0; q < 4; q++) acc[i][j][q] = 0.f;

    int g = lane >> 3, lr = lane & 7;
    int frow = lr + ((g & 1) << 3);
    int fcol = (g >> 1) << 3;

    // issue all chunk loads up-front (one commit group per chunk/stage)
#pragma unroll
    for (int c = 0; c < NCH; c++) {
        __nv_bfloat16* sA = sbase + c * STAGE;
        __nv_bfloat16* sBh = sA + TB;
        __nv_bfloat16* sBl = sBh + TB;
        int kc = c * KC;
#pragma unroll
        for (int idx = tid; idx < 1024; idx += 256) {
            int r = idx >> 3, cc = (idx & 7) * 8;
            cp16(smem_u32(&sA[r * ST + cc]), &Ab[(size_t)(bm + r) * K + kc + cc]);
            cp16(smem_u32(&sBh[r * ST + cc]), &Bh_blk[(size_t)r * K + kc + cc]);
            cp16(smem_u32(&sBl[r * ST + cc]), &Bl_blk[(size_t)r * K + kc + cc]);
        }
        CP_COMMIT();
    }

#pragma unroll
    for (int c = 0; c < NCH; c++) {
        if (NCH == 2 && c == 0) CP_WAIT(1);
        else CP_WAIT(0);
        __syncthreads();
        __nv_bfloat16* sA = sbase + c * STAGE;
        __nv_bfloat16* sBh = sA + TB;
        __nv_bfloat16* sBl = sBh + TB;
#pragma unroll
        for (int ks = 0; ks < 4; ks++) {
            int kcol = ks * 16 + fcol;
            uint32_t ah0[4], ah1[4];
            ldsm4(ah0, smem_u32(&sA[(warp_m * 32 + frow) * ST + kcol]));
            ldsm4(ah1, smem_u32(&sA[(warp_m * 32 + 16 + frow) * ST + kcol]));
#pragma unroll
            for (int tp = 0; tp < 4; tp++) {
                int brow = warp_n * 64 + tp * 16 + frow;
                uint32_t bh[4], bl[4];
                ldsm4(bh, smem_u32(&sBh[brow * ST + kcol]));
                ldsm4(bl, smem_u32(&sBl[brow * ST + kcol]));
                mma_bf16(acc[0][tp * 2 + 0], ah0, bh[0], bh[2]);
                mma_bf16(acc[0][tp * 2 + 1], ah0, bh[1], bh[3]);
                mma_bf16(acc[1][tp * 2 + 0], ah1, bh[0], bh[2]);
                mma_bf16(acc[1][tp * 2 + 1], ah1, bh[1], bh[3]);
                mma_bf16(acc[0][tp * 2 + 0], ah0, bl[0], bl[2]);
                mma_bf16(acc[0][tp * 2 + 1], ah0, bl[1], bl[3]);
                mma_bf16(acc[1][tp * 2 + 0], ah1, bl[0], bl[2]);
                mma_bf16(acc[1][tp * 2 + 1], ah1, bl[1], bl[3]);
            }
        }
    }

    int lr4 = lane >> 2, lc = (lane & 3) * 2;
#pragma unroll
    for (int tm = 0; tm < 2; tm++) {
#pragma unroll
        for (int half = 0; half < 2; half++) {
            int row = bm + warp_m * 32 + tm * 16 + lr4 + half * 8;
#pragma unroll
            for (int tn = 0; tn < 8; tn++) {
                int gc = bn + warp_n * 64 + tn * 8 + lc;
                float v0 = acc[tm][tn][half * 2 + 0];
                float v1 = acc[tm][tn][half * 2 + 1];
                if (FBIAS) { v0 += bias[gc]; v1 += bias[gc + 1]; }
                if (gc < 128) {  // xl half -> bf16
                    __nv_bfloat162 hv = __floats2bfloat162_rn(v0, v1);
                    *(uint32_t*)&ohi[(size_t)row * NH + gc] = *(uint32_t*)&hv;
                } else {         // xr half -> fp32
                    *(float2*)&outF[(size_t)row * NH + (gc - 128)] = make_float2(v0, v1);
                }
            }
        }
    }
}

// ---------------- fused GAT aggregation: warp per node, 4-wide, plain exp-sum ----------------
// e = att . lrelu(.) is a 128-term dot of small weights: |e| stays << 80, so exp() is
// safely in fp32 range without max-shifting (validated: rel_err 6.3e-5).
__device__ __forceinline__ float4 bf2f4(uint2 u) {
    __nv_bfloat162 p0 = *(__nv_bfloat162*)&u.x;
    __nv_bfloat162 p1 = *(__nv_bfloat162*)&u.y;
    float4 r;
    r.x = __bfloat162float(p0.x);
    r.y = __bfloat162float(p0.y);
    r.z = __bfloat162float(p1.x);
    r.w = __bfloat162float(p1.y);
    return r;
}
__global__ void gat_agg_kernel(const __nv_bfloat16* __restrict__ xlb,
                               const float* __restrict__ xr, const int* __restrict__ rowoff,
                               const int* __restrict__ csrc, const float* __restrict__ att,
                               const float* __restrict__ bias,
                               __nv_bfloat16* __restrict__ ohi,
                               const int* __restrict__ batch, float* __restrict__ pool,
                               float* __restrict__ cnt, float scale) {
    int node = blockIdx.x * 8 + (threadIdx.x >> 5);
    if (node >= NN) return;
    int lane = threadIdx.x & 31;
    const uint2* XB = (const uint2*)xlb;
    float4 xr4 = ((const float4*)xr)[(size_t)node * 32 + lane];
    float4 t = ((const float4*)att)[lane];
    int k = rowoff[node];
    int end = rowoff[node + 1];
    float s0 = 0.f, s1 = 0.f;
    float4 a0 = {0.f, 0.f, 0.f, 0.f}, a1 = {0.f, 0.f, 0.f, 0.f};
    for (; k + 4 <= end; k += 4) {
        int sa = csrc[k], sb = csrc[k + 1], sc = csrc[k + 2], sd = csrc[k + 3];
        float4 xA = bf2f4(XB[(size_t)sa * 32 + lane]);
        float4 xB = bf2f4(XB[(size_t)sb * 32 + lane]);
        float4 xC = bf2f4(XB[(size_t)sc * 32 + lane]);
        float4 xD = bf2f4(XB[(size_t)sd * 32 + lane]);
        float eA = lrelu(xA.x + xr4.x) * t.x + lrelu(xA.y + xr4.y) * t.y +
                   lrelu(xA.z + xr4.z) * t.z + lrelu(xA.w + xr4.w) * t.w;
        float eB = lrelu(xB.x + xr4.x) * t.x + lrelu(xB.y + xr4.y) * t.y +
                   lrelu(xB.z + xr4.z) * t.z + lrelu(xB.w + xr4.w) * t.w;
        float eC = lrelu(xC.x + xr4.x) * t.x + lrelu(xC.y + xr4.y) * t.y +
                   lrelu(xC.z + xr4.z) * t.z + lrelu(xC.w + xr4.w) * t.w;
        float eD = lrelu(xD.x + xr4.x) * t.x + lrelu(xD.y + xr4.y) * t.y +
                   lrelu(xD.z + xr4.z) * t.z + lrelu(xD.w + xr4.w) * t.w;
#pragma unroll
        for (int o = 16; o; o >>= 1) {
            eA += __shfl_xor_sync(0xFFFFFFFFu, eA, o);
            eB += __shfl_xor_sync(0xFFFFFFFFu, eB, o);
            eC += __shfl_xor_sync(0xFFFFFFFFu, eC, o);
            eD += __shfl_xor_sync(0xFFFFFFFFu, eD, o);
        }
        float wA = __expf(eA), wB = __expf(eB), wC = __expf(eC), wD = __expf(eD);
        s0 += wA + wC;
        s1 += wB + wD;
        a0.x += wA * xA.x + wC * xC.x;
        a0.y += wA * xA.y + wC * xC.y;
        a0.z += wA * xA.z + wC * xC.z;
        a0.w += wA * xA.w + wC * xC.w;
        a1.x += wB * xB.x + wD * xD.x;
        a1.y += wB * xB.y + wD * xD.y;
        a1.z += wB * xB.z + wD * xD.z;
        a1.w += wB * xB.w + wD * xD.w;
    }
    for (; k < end; k++) {
        int sn = csrc[k];
        float4 xA = bf2f4(XB[(size_t)sn * 32 + lane]);
        float eA = lrelu(xA.x + xr4.x) * t.x + lrelu(xA.y + xr4.y) * t.y +
                   lrelu(xA.z + xr4.z) * t.z + lrelu(xA.w + xr4.w) * t.w;
#pragma unroll
        for (int o = 16; o; o >>= 1) eA += __shfl_xor_sync(0xFFFFFFFFu, eA, o);
        float wA = __expf(eA);
        s0 += wA;
        a0.x += wA * xA.x;
        a0.y += wA * xA.y;
        a0.z += wA * xA.z;
        a0.w += wA * xA.w;
    }
    float s = s0 + s1;
    float inv = 1.f / (s + 1e-16f);
    float4 b4 = ((const float4*)bias)[lane];
    float4 r;
    r.x = fmaxf((a0.x + a1.x) * inv + b4.x, 0.f) * scale;
    r.y = fmaxf((a0.y + a1.y) * inv + b4.y, 0.f) * scale;
    r.z = fmaxf((a0.z + a1.z) * inv + b4.z, 0.f) * scale;
    r.w = fmaxf((a0.w + a1.w) * inv + b4.w, 0.f) * scale;
    if (ohi) {
        __nv_bfloat162 h01 = __floats2bfloat162_rn(r.x, r.y);
        __nv_bfloat162 h23 = __floats2bfloat162_rn(r.z, r.w);
        uint2 uh;
        uh.x = *(uint32_t*)&h01;
        uh.y = *(uint32_t*)&h23;
        ((uint2*)ohi)[(size_t)node * 32 + lane] = uh;
    }
    if (pool) {
        int gidx = batch[node];
        atomicAdd((float4*)(pool + (size_t)gidx * NH + lane * 4), r);
        if (lane == 0) atomicAdd(&cnt[gidx], 1.f);
    }
}

// ---------------- final MLP + layernorm ----------------
__global__ void mlp_kernel(const float* __restrict__ pool, const float* __restrict__ cnt,
                           const float* __restrict__ w1, const float* __restrict__ b1,
                           const float* __restrict__ w2, const float* __restrict__ b2,
                           const float* __restrict__ lng, const float* __restrict__ lnb,
                           float* __restrict__ out) {
    int g = blockIdx.x;
    int t = threadIdx.x;
    __shared__ float p[NH];
    __shared__ float z1[2 * NH];
    __shared__ float rs[8], rq[8];
    float inv = 1.f / fmaxf(cnt[g], 1.f);
    if (t < NH) p[t] = pool[g * NH + t] * inv;
    __syncthreads();
    float a = 0.f;
#pragma unroll 8
    for (int k = 0; k < NH; k++) a += p[k] * w1[k * (2 * NH) + t];
    z1[t] = fmaxf(a + b1[t], 0.f);
    __syncthreads();
    float z = 0.f;
#pragma unroll 8
    for (int k = 0; k < 2 * NH; k++) z += z1[k] * w2[k * NO + t];
    z += b2[t];
    float v = z, v2 = z * z;
#pragma unroll
    for (int o = 16; o; o >>= 1) {
        v += __shfl_xor_sync(0xFFFFFFFFu, v, o);
        v2 += __shfl_xor_sync(0xFFFFFFFFu, v2, o);
    }
    int wid = t >> 5, lane = t & 31;
    if (lane == 0) { rs[wid] = v; rq[wid] = v2; }
    __syncthreads();
    if (wid == 0) {
        float sv = lane < 8 ? rs[lane] : 0.f;
        float sq = lane < 8 ? rq[lane] : 0.f;
#pragma unroll
        for (int o = 4; o; o >>= 1) {
            sv += __shfl_xor_sync(0xFFFFFFFFu, sv, o);
            sq += __shfl_xor_sync(0xFFFFFFFFu, sq, o);
        }
        if (lane == 0) { rs[0] = sv; rq[0] = sq; }
    }
    __syncthreads();
    float mu = rs[0] * (1.f / NO);
    float var = rq[0] * (1.f / NO) - mu * mu;
    out[g * NO + t] = (z - mu) * rsqrtf(var + 1e-5f) * lng[t] + lnb[t];
}

// ---------------- host ----------------
extern "C" void kernel_launch(void* const* d_in, const int* in_sizes, int n_in,
                              void* d_out, int out_size) {
    const float* x = (const float*)d_in[0];
    const int* ei = (const int*)d_in[1];
    const int* src = ei;
    const int* dst = ei + NE;
    const int* batch = (const int*)d_in[2];
    const float* Wl[4] = {(const float*)d_in[3], (const float*)d_in[7],
                          (const float*)d_in[11], (const float*)d_in[15]};
    const float* Wr[4] = {(const float*)d_in[4], (const float*)d_in[8],
                          (const float*)d_in[12], (const float*)d_in[16]};
    const float* att[4] = {(const float*)d_in[5], (const float*)d_in[9],
                           (const float*)d_in[13], (const float*)d_in[17]};
    const float* bb[4] = {(const float*)d_in[6], (const float*)d_in[10],
                          (const float*)d_in[14], (const float*)d_in[18]};
    const float* res_w0 = (const float*)d_in[19];
    const float* res_b0 = (const float*)d_in[20];
    const float* res_w2 = (const float*)d_in[21];
    const float* res_b2 = (const float*)d_in[22];
    const float* mh1_w = (const float*)d_in[23];
    const float* mh1_b = (const float*)d_in[24];
    const float* mh2_w = (const float*)d_in[25];
    const float* mh2_b = (const float*)d_in[26];
    const float* ln_g = (const float*)d_in[27];
    const float* ln_b = (const float*)d_in[28];
    float* out = (float*)d_out;

    float *xr, *pool, *cnt, *beff;
    __nv_bfloat16 *xlb, *hb, *xb, *bfh, *bfl;
    int *rowoff, *cursor, *csrc;
    cudaGetSymbolAddress((void**)&xlb, g_xlb);
    cudaGetSymbolAddress((void**)&xr, g_xr);
    cudaGetSymbolAddress((void**)&hb, g_hb);
    cudaGetSymbolAddress((void**)&xb, g_xb);
    cudaGetSymbolAddress((void**)&bfh, g_bfh);
    cudaGetSymbolAddress((void**)&bfl, g_bfl);
    cudaGetSymbolAddress((void**)&beff, g_beff);
    cudaGetSymbolAddress((void**)&rowoff, g_rowoff);
    cudaGetSymbolAddress((void**)&cursor, g_cursor);
    cudaGetSymbolAddress((void**)&csrc, g_csrc);
    cudaGetSymbolAddress((void**)&pool, g_pool);
    cudaGetSymbolAddress((void**)&cnt, g_cnt);

    // ---- smem attrs (idempotent): 2 stages x 3 tiles x 18432 B ----
    const int SMEM_MM = 2 * 3 * 128 * 72 * 2;  // 110592
    cudaFuncSetAttribute(mm_gemm<64, false>, cudaFuncAttributeMaxDynamicSharedMemorySize,
                         SMEM_MM);
    cudaFuncSetAttribute(mm_gemm<128, false>, cudaFuncAttributeMaxDynamicSharedMemorySize,
                         SMEM_MM);
    cudaFuncSetAttribute(mm_gemm<128, true>, cudaFuncAttributeMaxDynamicSharedMemorySize,
                         SMEM_MM);

    const int GT = NP / 128;  // 313
    dim3 gf(GT, 2);
    const int AGG_BLK = (NN + 7) / 8;
    const int SLOT = 256 * 128;

    // ---- single side stream (teardown-safe topology): CSR chain then weight prep ----
    cudaStream_t s2;
    cudaEvent_t evF, evJ2, evJ3;
    cudaStreamCreateWithFlags(&s2, cudaStreamNonBlocking);
    cudaEventCreateWithFlags(&evF, cudaEventDisableTiming);
    cudaEventCreateWithFlags(&evJ2, cudaEventDisableTiming);
    cudaEventCreateWithFlags(&evJ3, cudaEventDisableTiming);
    cudaEventRecord(evF, 0);
    cudaStreamWaitEvent(s2, evF, 0);

    // s2 (phase A): CSR build -> evJ2 (pool init deferred to phase B; only agg-4 needs it)
    cudaMemsetAsync(cursor, 0, NN * sizeof(int), s2);
    hist_kernel<<<(NE + 255) / 256, 256, 0, s2>>>(dst, cursor);
    scan_kernel<<<1, 1024, 0, s2>>>(cursor, rowoff, cursor);
    fill_kernel<<<(NE + 255) / 256, 256, 0, s2>>>(src, dst, cursor, csrc);
    cudaEventRecord(evJ2, s2);

    // s2 (phase B): pool init + effective weights for layers 2..4 -> evJ3
    cudaMemsetAsync(pool, 0, NG * NH * sizeof(float), s2);
    cudaMemsetAsync(cnt, 0, NG * sizeof(float), s2);
    weff_kernel<<<128, 256, 0, s2>>>(res_w0, Wl[1], Wr[1], bfh + SLOT, bfl + SLOT);
    beff_kernel<<<1, 256, 0, s2>>>(res_b0, Wl[1], Wr[1], beff);
    pack_fused_kernel<<<(256 * NH + 255) / 256, 256, 0, s2>>>(Wl[2], Wr[2], bfh + 2 * SLOT,
                                                              bfl + 2 * SLOT, NH);
    weff_kernel<<<128, 256, 0, s2>>>(res_w2, Wl[3], Wr[3], bfh + 3 * SLOT, bfl + 3 * SLOT);
    beff_kernel<<<1, 256, 0, s2>>>(res_b2, Wl[3], Wr[3], beff + 256);
    cudaEventRecord(evJ3, s2);

    // main stream: layer-1 dependencies + layer-1 GEMM (overlaps with s2)
    pack_fused_kernel<<<(256 * NIN + 255) / 256, 256>>>(Wl[0], Wr[0], bfh, bfl, NIN);
    split_x_kernel<<<(NN * NIN + 255) / 256, 256>>>(x, xb);
    mm_gemm<64, false><<<gf, 256, SMEM_MM>>>(xb, bfh, bfl, nullptr, xr, xlb);

    // join CSR before first agg; join weights before layer-2 GEMM
    cudaStreamWaitEvent(0, evJ2, 0);
    gat_agg_kernel<<<AGG_BLK, 256>>>(xlb, xr, rowoff, csrc, att[0], bb[0], hb, nullptr, nullptr,
                                     nullptr, 1.f);
    cudaStreamWaitEvent(0, evJ3, 0);
    // layer 2 (residual folded into effective weights + beff bias)
    mm_gemm<128, true><<<gf, 256, SMEM_MM>>>(hb, bfh + SLOT, bfl + SLOT, beff, xr, xlb);
    gat_agg_kernel<<<AGG_BLK, 256>>>(xlb, xr, rowoff, csrc, att[1], bb[1], hb, nullptr, nullptr,
                                     nullptr, 2.f);
    // layer 3
    mm_gemm<128, false><<<gf, 256, SMEM_MM>>>(hb, bfh + 2 * SLOT, bfl + 2 * SLOT, nullptr, xr,
                                              xlb);
    gat_agg_kernel<<<AGG_BLK, 256>>>(xlb, xr, rowoff, csrc, att[2], bb[2], hb, nullptr, nullptr,
                                     nullptr, 1.f);
    // layer 4 (residual folded; agg fuses pooling)
    mm_gemm<128, true><<<gf, 256, SMEM_MM>>>(hb, bfh + 3 * SLOT, bfl + 3 * SLOT, beff + 256, xr,
                                             xlb);
    gat_agg_kernel<<<AGG_BLK, 256>>>(xlb, xr, rowoff, csrc, att[3], bb[3], nullptr, batch, pool,
                                     cnt, 2.f);

    // MLP + layernorm
    mlp_kernel<<<NG, 256>>>(pool, cnt, mh1_w, mh1_b, mh2_w, mh2_b, ln_g, ln_b, out);
}

// round 16
// speedup vs baseline: 1.0723x; 1.0209x over previous
#include <cuda_runtime.h>
#include <cuda_bf16.h>
#include <math.h>
#include <stdint.h>

#define NN 40000
#define NP 40064          // padded rows (313 * 128)
#define NE 640000
#define NG 128
#define NIN 64
#define NH 128
#define NO 256
#define SCB 40            // scan blocks (40*1024 >= NN)

// ---------------- scratch (device globals; no allocation allowed) ----------------
__device__ __align__(16) __nv_bfloat16 g_xlb[NP * NH];   // xl in bf16 (gathered per edge)
__device__ __align__(16) __nv_bfloat16 g_xrb[NP * NH];   // xr in bf16 (read per node)
__device__ __align__(16) __nv_bfloat16 g_hb[NP * NH];    // agg output (bf16 activations)
__device__ __align__(16) __nv_bfloat16 g_xb[NP * NIN];   // input x in bf16
__device__ __align__(16) __nv_bfloat16 g_bfh[4][256 * 128];  // per-layer effective [N,K] hi
__device__ __align__(16) __nv_bfloat16 g_bfl[4][256 * 128];  // lo
__device__ float g_beff[2][256];                             // folded residual bias terms
__device__ int   g_rowoff[NN + 1];
__device__ int   g_cursor[NN];
__device__ int   g_bsum[SCB];
__device__ int   g_csrc[NE];
__device__ float g_pool[NG * NH];
__device__ float g_cnt[NG];

__device__ __forceinline__ float lrelu(float v) { return v > 0.f ? v : 0.2f * v; }

__device__ __forceinline__ uint32_t smem_u32(const void* p) {
    uint32_t a;
    asm("{ .reg .u64 t; cvta.to.shared.u64 t, %1; cvt.u32.u64 %0, t; }" : "=r"(a) : "l"(p));
    return a;
}
__device__ __forceinline__ void ldsm4(uint32_t* r, uint32_t addr) {
    asm volatile("ldmatrix.sync.aligned.m8n8.x4.shared.b16 {%0,%1,%2,%3}, [%4];"
                 : "=r"(r[0]), "=r"(r[1]), "=r"(r[2]), "=r"(r[3]) : "r"(addr));
}
__device__ __forceinline__ void mma_bf16(float* d, const uint32_t* a, uint32_t b0, uint32_t b1) {
    asm volatile(
        "mma.sync.aligned.m16n8k16.row.col.f32.bf16.bf16.f32 "
        "{%0,%1,%2,%3}, {%4,%5,%6,%7}, {%8,%9}, {%0,%1,%2,%3};"
        : "+f"(d[0]), "+f"(d[1]), "+f"(d[2]), "+f"(d[3])
        : "r"(a[0]), "r"(a[1]), "r"(a[2]), "r"(a[3]), "r"(b0), "r"(b1));
}
__device__ __forceinline__ void cp16(uint32_t dst, const void* src) {
    asm volatile("cp.async.cg.shared.global [%0], [%1], 16;" :: "r"(dst), "l"(src));
}
#define CP_COMMIT() asm volatile("cp.async.commit_group;" ::: "memory")
#define CP_WAIT(n) asm volatile("cp.async.wait_group %0;" :: "n"(n) : "memory")

// ---------------- CSR build ----------------
__global__ void hist_kernel(const int* __restrict__ dst, int* __restrict__ cnt) {
    int i = blockIdx.x * blockDim.x + threadIdx.x;
    if (i < NE) atomicAdd(&cnt[dst[i]], 1);
}
// pass1: per-block sums of cnt
__global__ void scan1_kernel(const int* __restrict__ cnt, int* __restrict__ bsum) {
    __shared__ int ws[32];
    int i = blockIdx.x * 1024 + threadIdx.x;
    int lane = threadIdx.x & 31, wid = threadIdx.x >> 5;
    int v = (i < NN) ? cnt[i] : 0;
#pragma unroll
    for (int o = 16; o; o >>= 1) v += __shfl_xor_sync(0xFFFFFFFFu, v, o);
    if (lane == 0) ws[wid] = v;
    __syncthreads();
    if (wid == 0) {
        int s = ws[lane];
#pragma unroll
        for (int o = 16; o; o >>= 1) s += __shfl_xor_sync(0xFFFFFFFFu, s, o);
        if (lane == 0) bsum[blockIdx.x] = s;
    }
}
// pass2: tiny exclusive scan of SCB block sums (1 warp)
__global__ void scan2_kernel(int* __restrict__ bsum) {
    if (threadIdx.x == 0) {
        int acc = 0;
        for (int b = 0; b < SCB; b++) {
            int v = bsum[b];
            bsum[b] = acc;
            acc += v;
        }
    }
}
// pass3: per-block exclusive scan + block offset -> rowoff, cursor
__global__ void scan3_kernel(const int* __restrict__ cnt, const int* __restrict__ bsum,
                             int* __restrict__ rowoff, int* __restrict__ cursor) {
    __shared__ int ws[32];
    int i = blockIdx.x * 1024 + threadIdx.x;
    int lane = threadIdx.x & 31, wid = threadIdx.x >> 5;
    int v = (i < NN) ? cnt[i] : 0;
    int x = v;
#pragma unroll
    for (int o = 1; o < 32; o <<= 1) {
        int y = __shfl_up_sync(0xFFFFFFFFu, x, o);
        if (lane >= o) x += y;
    }
    if (lane == 31) ws[wid] = x;
    __syncthreads();
    if (wid == 0) {
        int w = ws[lane];
#pragma unroll
        for (int o = 1; o < 32; o <<= 1) {
            int y = __shfl_up_sync(0xFFFFFFFFu, w, o);
            if (lane >= o) w += y;
        }
        ws[lane] = w;
    }
    __syncthreads();
    int excl = x - v + (wid > 0 ? ws[wid - 1] : 0) + bsum[blockIdx.x];
    if (i < NN) { rowoff[i] = excl; cursor[i] = excl; }
    if (blockIdx.x == 0 && threadIdx.x == 0) rowoff[NN] = NE;
}
__global__ void fill_kernel(const int* __restrict__ src, const int* __restrict__ dst,
                            int* __restrict__ cursor, int* __restrict__ csrc) {
    int i = blockIdx.x * blockDim.x + threadIdx.x;
    if (i >= NE) return;
    int pos = atomicAdd(&cursor[dst[i]], 1);
    csrc[pos] = src[i];
}

// ---------------- weight pack+split (transposed to [N,K]) ----------------
__global__ void pack_fused_kernel(const float* __restrict__ Wl, const float* __restrict__ Wr,
                                  __nv_bfloat16* __restrict__ bh, __nv_bfloat16* __restrict__ bl,
                                  int K) {
    int i = blockIdx.x * blockDim.x + threadIdx.x;
    if (i >= 256 * K) return;
    int n = i / K, k = i % K;
    float v = (n < 128) ? Wl[k * 128 + n] : Wr[k * 128 + (n - 128)];
    __nv_bfloat16 h = __float2bfloat16(v);
    bh[i] = h;
    bl[i] = __float2bfloat16(v - __bfloat162float(h));
}
// Weff = (res_w + I) @ [Wl|Wr], stored [n*128 + k] split hi/lo. grid 128, block 256.
__global__ void weff_kernel(const float* __restrict__ res_w, const float* __restrict__ Wl,
                            const float* __restrict__ Wr, __nv_bfloat16* __restrict__ bh,
                            __nv_bfloat16* __restrict__ bl) {
    __shared__ float a[128];
    int r = blockIdx.x;
    int n = threadIdx.x;
    if (n < 128) {
        float v = res_w[r * 128 + n];
        if (n == r) v += 1.f;
        a[n] = v;
    }
    __syncthreads();
    const float* Wp = (n < 128) ? (Wl + n) : (Wr + (n - 128));
    float s = 0.f;
#pragma unroll 8
    for (int k = 0; k < 128; k++) s += a[k] * Wp[k * 128];
    __nv_bfloat16 h = __float2bfloat16(s);
    bh[n * 128 + r] = h;
    bl[n * 128 + r] = __float2bfloat16(s - __bfloat162float(h));
}
// beff[n] = res_b @ [Wl|Wr] column n. 1 block, 256 threads.
__global__ void beff_kernel(const float* __restrict__ res_b, const float* __restrict__ Wl,
                            const float* __restrict__ Wr, float* __restrict__ beff) {
    __shared__ float b[128];
    int n = threadIdx.x;
    if (n < 128) b[n] = res_b[n];
    __syncthreads();
    const float* Wp = (n < 128) ? (Wl + n) : (Wr + (n - 128));
    float s = 0.f;
#pragma unroll 8
    for (int k = 0; k < 128; k++) s += b[k] * Wp[k * 128];
    beff[n] = s;
}
__global__ void split_x_kernel(const float* __restrict__ x, __nv_bfloat16* __restrict__ hi) {
    int i = blockIdx.x * blockDim.x + threadIdx.x;
    if (i >= NN * NIN) return;
    hi[i] = __float2bfloat16(x[i]);
}

// ---------------- tensor-core GEMM via mma.sync (2-term, 2-stage cp.async pipeline) ----------------
// out cols 0-127 -> bf16 xl (ohi), cols 128-255 -> bf16 xr (oxr); optional fp32 bias[256].
template <int K, bool FBIAS>
__global__ void __launch_bounds__(256, 2) mm_gemm(
    const __nv_bfloat16* __restrict__ Ab,
    const __nv_bfloat16* __restrict__ Bh, const __nv_bfloat16* __restrict__ Bl,
    const float* __restrict__ bias, __nv_bfloat16* __restrict__ oxr,
    __nv_bfloat16* __restrict__ ohi) {
    extern __shared__ char smem[];
    constexpr int KC = 64, ST = 72;
    constexpr int TB = 128 * ST;      // elems per tile
    constexpr int STAGE = 3 * TB;     // elems per stage (A, Bh, Bl)
    constexpr int NCH = K / KC;       // 1 or 2 chunks
    __nv_bfloat16* sbase = (__nv_bfloat16*)smem;
    int tid = threadIdx.x, lane = tid & 31, wid = tid >> 5;
    int warp_m = wid & 3, warp_n = wid >> 2;
    int bm = blockIdx.x * 128, bn = blockIdx.y * 128;
    const __nv_bfloat16* Bh_blk = Bh + (size_t)bn * K;
    const __nv_bfloat16* Bl_blk = Bl + (size_t)bn * K;

    float acc[2][8][4];
#pragma unroll
    for (int i = 0; i < 2; i++)
#pragma unroll
        for (int j = 0; j < 8; j++)
#pragma unroll
            for (int q = 0; q < 4; q++) acc[i][j][q] = 0.f;

    int g = lane >> 3, lr = lane & 7;
    int frow = lr + ((g & 1) << 3);
    int fcol = (g >> 1) << 3;

    // issue all chunk loads up-front (one commit group per chunk/stage)
#pragma unroll
    for (int c = 0; c < NCH; c++) {
        __nv_bfloat16* sA = sbase + c * STAGE;
        __nv_bfloat16* sBh = sA + TB;
        __nv_bfloat16* sBl = sBh + TB;
        int kc = c * KC;
#pragma unroll
        for (int idx = tid; idx < 1024; idx += 256) {
            int r = idx >> 3, cc = (idx & 7) * 8;
            cp16(smem_u32(&sA[r * ST + cc]), &Ab[(size_t)(bm + r) * K + kc + cc]);
            cp16(smem_u32(&sBh[r * ST + cc]), &Bh_blk[(size_t)r * K + kc + cc]);
            cp16(smem_u32(&sBl[r * ST + cc]), &Bl_blk[(size_t)r * K + kc + cc]);
        }
        CP_COMMIT();
    }

#pragma unroll
    for (int c = 0; c < NCH; c++) {
        if (NCH == 2 && c == 0) CP_WAIT(1);
        else CP_WAIT(0);
        __syncthreads();
        __nv_bfloat16* sA = sbase + c * STAGE;
        __nv_bfloat16* sBh = sA + TB;
        __nv_bfloat16* sBl = sBh + TB;
#pragma unroll
        for (int ks = 0; ks < 4; ks++) {
            int kcol = ks * 16 + fcol;
            uint32_t ah0[4], ah1[4];
            ldsm4(ah0, smem_u32(&sA[(warp_m * 32 + frow) * ST + kcol]));
            ldsm4(ah1, smem_u32(&sA[(warp_m * 32 + 16 + frow) * ST + kcol]));
#pragma unroll
            for (int tp = 0; tp < 4; tp++) {
                int brow = warp_n * 64 + tp * 16 + frow;
                uint32_t bh[4], bl[4];
                ldsm4(bh, smem_u32(&sBh[brow * ST + kcol]));
                ldsm4(bl, smem_u32(&sBl[brow * ST + kcol]));
                mma_bf16(acc[0][tp * 2 + 0], ah0, bh[0], bh[2]);
                mma_bf16(acc[0][tp * 2 + 1], ah0, bh[1], bh[3]);
                mma_bf16(acc[1][tp * 2 + 0], ah1, bh[0], bh[2]);
                mma_bf16(acc[1][tp * 2 + 1], ah1, bh[1], bh[3]);
                mma_bf16(acc[0][tp * 2 + 0], ah0, bl[0], bl[2]);
                mma_bf16(acc[0][tp * 2 + 1], ah0, bl[1], bl[3]);
                mma_bf16(acc[1][tp * 2 + 0], ah1, bl[0], bl[2]);
                mma_bf16(acc[1][tp * 2 + 1], ah1, bl[1], bl[3]);
            }
        }
    }

    int lr4 = lane >> 2, lc = (lane & 3) * 2;
#pragma unroll
    for (int tm = 0; tm < 2; tm++) {
#pragma unroll
        for (int half = 0; half < 2; half++) {
            int row = bm + warp_m * 32 + tm * 16 + lr4 + half * 8;
#pragma unroll
            for (int tn = 0; tn < 8; tn++) {
                int gc = bn + warp_n * 64 + tn * 8 + lc;
                float v0 = acc[tm][tn][half * 2 + 0];
                float v1 = acc[tm][tn][half * 2 + 1];
                if (FBIAS) { v0 += bias[gc]; v1 += bias[gc + 1]; }
                __nv_bfloat162 hv = __floats2bfloat162_rn(v0, v1);
                if (gc < 128) {
                    *(uint32_t*)&ohi[(size_t)row * NH + gc] = *(uint32_t*)&hv;
                } else {
                    *(uint32_t*)&oxr[(size_t)row * NH + (gc - 128)] = *(uint32_t*)&hv;
                }
            }
        }
    }
}

// ---------------- fused GAT aggregation: warp per node, 4-wide, plain exp-sum ----------------
// e = att . lrelu(.) is a 128-term dot of small weights: |e| stays << 80, so exp() is
// safely in fp32 range without max-shifting (validated: rel_err 6.3e-5).
__device__ __forceinline__ float4 bf2f4(uint2 u) {
    __nv_bfloat162 p0 = *(__nv_bfloat162*)&u.x;
    __nv_bfloat162 p1 = *(__nv_bfloat162*)&u.y;
    float4 r;
    r.x = __bfloat162float(p0.x);
    r.y = __bfloat162float(p0.y);
    r.z = __bfloat162float(p1.x);
    r.w = __bfloat162float(p1.y);
    return r;
}
__global__ void gat_agg_kernel(const __nv_bfloat16* __restrict__ xlb,
                               const __nv_bfloat16* __restrict__ xrb,
                               const int* __restrict__ rowoff,
                               const int* __restrict__ csrc, const float* __restrict__ att,
                               const float* __restrict__ bias,
                               __nv_bfloat16* __restrict__ ohi,
                               const int* __restrict__ batch, float* __restrict__ pool,
                               float* __restrict__ cnt, float scale) {
    int node = blockIdx.x * 8 + (threadIdx.x >> 5);
    if (node >= NN) return;
    int lane = threadIdx.x & 31;
    const uint2* XB = (const uint2*)xlb;
    float4 xr4 = bf2f4(((const uint2*)xrb)[(size_t)node * 32 + lane]);
    float4 t = ((const float4*)att)[lane];
    int k = rowoff[node];
    int end = rowoff[node + 1];
    float s0 = 0.f, s1 = 0.f;
    float4 a0 = {0.f, 0.f, 0.f, 0.f}, a1 = {0.f, 0.f, 0.f, 0.f};
    for (; k + 4 <= end; k += 4) {
        int sa = csrc[k], sb = csrc[k + 1], sc = csrc[k + 2], sd = csrc[k + 3];
        float4 xA = bf2f4(XB[(size_t)sa * 32 + lane]);
        float4 xB = bf2f4(XB[(size_t)sb * 32 + lane]);
        float4 xC = bf2f4(XB[(size_t)sc * 32 + lane]);
        float4 xD = bf2f4(XB[(size_t)sd * 32 + lane]);
        float eA = lrelu(xA.x + xr4.x) * t.x + lrelu(xA.y + xr4.y) * t.y +
                   lrelu(xA.z + xr4.z) * t.z + lrelu(xA.w + xr4.w) * t.w;
        float eB = lrelu(xB.x + xr4.x) * t.x + lrelu(xB.y + xr4.y) * t.y +
                   lrelu(xB.z + xr4.z) * t.z + lrelu(xB.w + xr4.w) * t.w;
        float eC = lrelu(xC.x + xr4.x) * t.x + lrelu(xC.y + xr4.y) * t.y +
                   lrelu(xC.z + xr4.z) * t.z + lrelu(xC.w + xr4.w) * t.w;
        float eD = lrelu(xD.x + xr4.x) * t.x + lrelu(xD.y + xr4.y) * t.y +
                   lrelu(xD.z + xr4.z) * t.z + lrelu(xD.w + xr4.w) * t.w;
#pragma unroll
        for (int o = 16; o; o >>= 1) {
            eA += __shfl_xor_sync(0xFFFFFFFFu, eA, o);
            eB += __shfl_xor_sync(0xFFFFFFFFu, eB, o);
            eC += __shfl_xor_sync(0xFFFFFFFFu, eC, o);
            eD += __shfl_xor_sync(0xFFFFFFFFu, eD, o);
        }
        float wA = __expf(eA), wB = __expf(eB), wC = __expf(eC), wD = __expf(eD);
        s0 += wA + wC;
        s1 += wB + wD;
        a0.x += wA * xA.x + wC * xC.x;
        a0.y += wA * xA.y + wC * xC.y;
        a0.z += wA * xA.z + wC * xC.z;
        a0.w += wA * xA.w + wC * xC.w;
        a1.x += wB * xB.x + wD * xD.x;
        a1.y += wB * xB.y + wD * xD.y;
        a1.z += wB * xB.z + wD * xD.z;
        a1.w += wB * xB.w + wD * xD.w;
    }
    for (; k < end; k++) {
        int sn = csrc[k];
        float4 xA = bf2f4(XB[(size_t)sn * 32 + lane]);
        float eA = lrelu(xA.x + xr4.x) * t.x + lrelu(xA.y + xr4.y) * t.y +
                   lrelu(xA.z + xr4.z) * t.z + lrelu(xA.w + xr4.w) * t.w;
#pragma unroll
        for (int o = 16; o; o >>= 1) eA += __shfl_xor_sync(0xFFFFFFFFu, eA, o);
        float wA = __expf(eA);
        s0 += wA;
        a0.x += wA * xA.x;
        a0.y += wA * xA.y;
        a0.z += wA * xA.z;
        a0.w += wA * xA.w;
    }
    float s = s0 + s1;
    float inv = 1.f / (s + 1e-16f);
    float4 b4 = ((const float4*)bias)[lane];
    float4 r;
    r.x = fmaxf((a0.x + a1.x) * inv + b4.x, 0.f) * scale;
    r.y = fmaxf((a0.y + a1.y) * inv + b4.y, 0.f) * scale;
    r.z = fmaxf((a0.z + a1.z) * inv + b4.z, 0.f) * scale;
    r.w = fmaxf((a0.w + a1.w) * inv + b4.w, 0.f) * scale;
    if (ohi) {
        __nv_bfloat162 h01 = __floats2bfloat162_rn(r.x, r.y);
        __nv_bfloat162 h23 = __floats2bfloat162_rn(r.z, r.w);
        uint2 uh;
        uh.x = *(uint32_t*)&h01;
        uh.y = *(uint32_t*)&h23;
        ((uint2*)ohi)[(size_t)node * 32 + lane] = uh;
    }
    if (pool) {
        int gidx = batch[node];
        atomicAdd((float4*)(pool + (size_t)gidx * NH + lane * 4), r);
        if (lane == 0) atomicAdd(&cnt[gidx], 1.f);
    }
}

// ---------------- final MLP + layernorm ----------------
__global__ void mlp_kernel(const float* __restrict__ pool, const float* __restrict__ cnt,
                           const float* __restrict__ w1, const float* __restrict__ b1,
                           const float* __restrict__ w2, const float* __restrict__ b2,
                           const float* __restrict__ lng, const float* __restrict__ lnb,
                           float* __restrict__ out) {
    int g = blockIdx.x;
    int t = threadIdx.x;
    __shared__ float p[NH];
    __shared__ float z1[2 * NH];
    __shared__ float rs[8], rq[8];
    float inv = 1.f / fmaxf(cnt[g], 1.f);
    if (t < NH) p[t] = pool[g * NH + t] * inv;
    __syncthreads();
    float a = 0.f;
#pragma unroll 8
    for (int k = 0; k < NH; k++) a += p[k] * w1[k * (2 * NH) + t];
    z1[t] = fmaxf(a + b1[t], 0.f);
    __syncthreads();
    float z = 0.f;
#pragma unroll 8
    for (int k = 0; k < 2 * NH; k++) z += z1[k] * w2[k * NO + t];
    z += b2[t];
    float v = z, v2 = z * z;
#pragma unroll
    for (int o = 16; o; o >>= 1) {
        v += __shfl_xor_sync(0xFFFFFFFFu, v, o);
        v2 += __shfl_xor_sync(0xFFFFFFFFu, v2, o);
    }
    int wid = t >> 5, lane = t & 31;
    if (lane == 0) { rs[wid] = v; rq[wid] = v2; }
    __syncthreads();
    if (wid == 0) {
        float sv = lane < 8 ? rs[lane] : 0.f;
        float sq = lane < 8 ? rq[lane] : 0.f;
#pragma unroll
        for (int o = 4; o; o >>= 1) {
            sv += __shfl_xor_sync(0xFFFFFFFFu, sv, o);
            sq += __shfl_xor_sync(0xFFFFFFFFu, sq, o);
        }
        if (lane == 0) { rs[0] = sv; rq[0] = sq; }
    }
    __syncthreads();
    float mu = rs[0] * (1.f / NO);
    float var = rq[0] * (1.f / NO) - mu * mu;
    out[g * NO + t] = (z - mu) * rsqrtf(var + 1e-5f) * lng[t] + lnb[t];
}

// ---------------- host ----------------
extern "C" void kernel_launch(void* const* d_in, const int* in_sizes, int n_in,
                              void* d_out, int out_size) {
    const float* x = (const float*)d_in[0];
    const int* ei = (const int*)d_in[1];
    const int* src = ei;
    const int* dst = ei + NE;
    const int* batch = (const int*)d_in[2];
    const float* Wl[4] = {(const float*)d_in[3], (const float*)d_in[7],
                          (const float*)d_in[11], (const float*)d_in[15]};
    const float* Wr[4] = {(const float*)d_in[4], (const float*)d_in[8],
                          (const float*)d_in[12], (const float*)d_in[16]};
    const float* att[4] = {(const float*)d_in[5], (const float*)d_in[9],
                           (const float*)d_in[13], (const float*)d_in[17]};
    const float* bb[4] = {(const float*)d_in[6], (const float*)d_in[10],
                          (const float*)d_in[14], (const float*)d_in[18]};
    const float* res_w0 = (const float*)d_in[19];
    const float* res_b0 = (const float*)d_in[20];
    const float* res_w2 = (const float*)d_in[21];
    const float* res_b2 = (const float*)d_in[22];
    const float* mh1_w = (const float*)d_in[23];
    const float* mh1_b = (const float*)d_in[24];
    const float* mh2_w = (const float*)d_in[25];
    const float* mh2_b = (const float*)d_in[26];
    const float* ln_g = (const float*)d_in[27];
    const float* ln_b = (const float*)d_in[28];
    float* out = (float*)d_out;

    float *pool, *cnt, *beff;
    __nv_bfloat16 *xlb, *xrb, *hb, *xb, *bfh, *bfl;
    int *rowoff, *cursor, *bsum, *csrc;
    cudaGetSymbolAddress((void**)&xlb, g_xlb);
    cudaGetSymbolAddress((void**)&xrb, g_xrb);
    cudaGetSymbolAddress((void**)&hb, g_hb);
    cudaGetSymbolAddress((void**)&xb, g_xb);
    cudaGetSymbolAddress((void**)&bfh, g_bfh);
    cudaGetSymbolAddress((void**)&bfl, g_bfl);
    cudaGetSymbolAddress((void**)&beff, g_beff);
    cudaGetSymbolAddress((void**)&rowoff, g_rowoff);
    cudaGetSymbolAddress((void**)&cursor, g_cursor);
    cudaGetSymbolAddress((void**)&bsum, g_bsum);
    cudaGetSymbolAddress((void**)&csrc, g_csrc);
    cudaGetSymbolAddress((void**)&pool, g_pool);
    cudaGetSymbolAddress((void**)&cnt, g_cnt);

    // ---- smem attrs (idempotent): 2 stages x 3 tiles x 18432 B ----
    const int SMEM_MM = 2 * 3 * 128 * 72 * 2;  // 110592
    cudaFuncSetAttribute(mm_gemm<64, false>, cudaFuncAttributeMaxDynamicSharedMemorySize,
                         SMEM_MM);
    cudaFuncSetAttribute(mm_gemm<128, false>, cudaFuncAttributeMaxDynamicSharedMemorySize,
                         SMEM_MM);
    cudaFuncSetAttribute(mm_gemm<128, true>, cudaFuncAttributeMaxDynamicSharedMemorySize,
                         SMEM_MM);

    const int GT = NP / 128;  // 313
    dim3 gf(GT, 2);
    const int AGG_BLK = (NN + 7) / 8;
    const int SLOT = 256 * 128;

    // ---- single side stream (teardown-safe topology): CSR chain then weight prep ----
    cudaStream_t s2;
    cudaEvent_t evF, evJ2, evJ3;
    cudaStreamCreateWithFlags(&s2, cudaStreamNonBlocking);
    cudaEventCreateWithFlags(&evF, cudaEventDisableTiming);
    cudaEventCreateWithFlags(&evJ2, cudaEventDisableTiming);
    cudaEventCreateWithFlags(&evJ3, cudaEventDisableTiming);
    cudaEventRecord(evF, 0);
    cudaStreamWaitEvent(s2, evF, 0);

    // s2 (phase A): CSR build (multi-block scan) -> evJ2
    cudaMemsetAsync(cursor, 0, NN * sizeof(int), s2);
    hist_kernel<<<(NE + 255) / 256, 256, 0, s2>>>(dst, cursor);
    scan1_kernel<<<SCB, 1024, 0, s2>>>(cursor, bsum);
    scan2_kernel<<<1, 32, 0, s2>>>(bsum);
    scan3_kernel<<<SCB, 1024, 0, s2>>>(cursor, bsum, rowoff, cursor);
    fill_kernel<<<(NE + 255) / 256, 256, 0, s2>>>(src, dst, cursor, csrc);
    cudaEventRecord(evJ2, s2);

    // s2 (phase B): pool init + effective weights for layers 2..4 -> evJ3
    cudaMemsetAsync(pool, 0, NG * NH * sizeof(float), s2);
    cudaMemsetAsync(cnt, 0, NG * sizeof(float), s2);
    weff_kernel<<<128, 256, 0, s2>>>(res_w0, Wl[1], Wr[1], bfh + SLOT, bfl + SLOT);
    beff_kernel<<<1, 256, 0, s2>>>(res_b0, Wl[1], Wr[1], beff);
    pack_fused_kernel<<<(256 * NH + 255) / 256, 256, 0, s2>>>(Wl[2], Wr[2], bfh + 2 * SLOT,
                                                              bfl + 2 * SLOT, NH);
    weff_kernel<<<128, 256, 0, s2>>>(res_w2, Wl[3], Wr[3], bfh + 3 * SLOT, bfl + 3 * SLOT);
    beff_kernel<<<1, 256, 0, s2>>>(res_b2, Wl[3], Wr[3], beff + 256);
    cudaEventRecord(evJ3, s2);

    // main stream: layer-1 dependencies + layer-1 GEMM (overlaps with s2)
    pack_fused_kernel<<<(256 * NIN + 255) / 256, 256>>>(Wl[0], Wr[0], bfh, bfl, NIN);
    split_x_kernel<<<(NN * NIN + 255) / 256, 256>>>(x, xb);
    mm_gemm<64, false><<<gf, 256, SMEM_MM>>>(xb, bfh, bfl, nullptr, xrb, xlb);

    // join CSR before first agg; join weights before layer-2 GEMM
    cudaStreamWaitEvent(0, evJ2, 0);
    gat_agg_kernel<<<AGG_BLK, 256>>>(xlb, xrb, rowoff, csrc, att[0], bb[0], hb, nullptr,
                                     nullptr, nullptr, 1.f);
    cudaStreamWaitEvent(0, evJ3, 0);
    // layer 2 (residual folded into effective weights + beff bias)
    mm_gemm<128, true><<<gf, 256, SMEM_MM>>>(hb, bfh + SLOT, bfl + SLOT, beff, xrb, xlb);
    gat_agg_kernel<<<AGG_BLK, 256>>>(xlb, xrb, rowoff, csrc, att[1], bb[1], hb, nullptr,
                                     nullptr, nullptr, 2.f);
    // layer 3
    mm_gemm<128, false><<<gf, 256, SMEM_MM>>>(hb, bfh + 2 * SLOT, bfl + 2 * SLOT, nullptr, xrb,
                                              xlb);
    gat_agg_kernel<<<AGG_BLK, 256>>>(xlb, xrb, rowoff, csrc, att[2], bb[2], hb, nullptr,
                                     nullptr, nullptr, 1.f);
    // layer 4 (residual folded; agg fuses pooling)
    mm_gemm<128, true><<<gf, 256, SMEM_MM>>>(hb, bfh + 3 * SLOT, bfl + 3 * SLOT, beff + 256,
                                             xrb, xlb);
    gat_agg_kernel<<<AGG_BLK, 256>>>(xlb, xrb, rowoff, csrc, att[3], bb[3], nullptr, batch,
                                     pool, cnt, 2.f);

    // MLP + layernorm
    mlp_kernel<<<NG, 256>>>(pool, cnt, mh1_w, mh1_b, mh2_w, mh2_b, ln_g, ln_b, out);
}